// round 1
// baseline (speedup 1.0000x reference)
#include <cuda_runtime.h>
#include <math.h>

#define N    16384
#define DDIM 512
#define BM   128
#define BN   128
#define BK   32
#define BMP  (BM + 4)   // padded row stride (keeps 16B alignment: 132*4=528 bytes)
#define NTILE (N / BN)  // 128

// Scratch: per-tile (max, sumexp) partials, laid out [index][tile] for coalesced stage-2 reads.
__device__ float2 g_rowPart[(size_t)N * NTILE];  // 16 MB
__device__ float2 g_colPart[(size_t)N * NTILE];  // 16 MB
__device__ float  g_contrib[N];

// ---------------------------------------------------------------------------
// Stage 1: fused tiled GEMM + per-tile LSE partials.
// Grid (NTILE, NTILE), 256 threads. Each block: 128x128 logits tile, K=512.
// ---------------------------------------------------------------------------
__global__ void __launch_bounds__(256)
clip_gemm_lse_part(const float* __restrict__ A,   // image [N, D]
                   const float* __restrict__ B,   // text  [N, D]
                   const float* __restrict__ scale_p)
{
    __shared__ float smem[2 * BK * BMP];          // 33.8 KB, reused for col partials
    float* As = smem;                             // As[k][row]
    float* Bs = smem + BK * BMP;                  // Bs[k][col]

    const int tid = threadIdx.x;
    const int tx  = tid & 15;        // 0..15 -> column groups
    const int ty  = tid >> 4;        // 0..15 -> row groups

    const float* Ag = A + (size_t)blockIdx.y * BM * DDIM;
    const float* Bg = B + (size_t)blockIdx.x * BN * DDIM;

    float acc[8][8];
    #pragma unroll
    for (int i = 0; i < 8; i++)
        #pragma unroll
        for (int j = 0; j < 8; j++)
            acc[i][j] = 0.0f;

    const int lr = tid >> 3;          // 0..31 (row within 32-row chunk)
    const int lk = (tid & 7) * 4;     // 0,4,...,28 (k offset)

    for (int kb = 0; kb < DDIM; kb += BK) {
        // ---- load 128x32 A and B tiles (transposed into [k][row]) ----
        #pragma unroll
        for (int it = 0; it < 4; it++) {
            const int row = lr + it * 32;
            float4 av = *(const float4*)(Ag + (size_t)row * DDIM + kb + lk);
            float4 bv = *(const float4*)(Bg + (size_t)row * DDIM + kb + lk);
            As[(lk + 0) * BMP + row] = av.x;
            As[(lk + 1) * BMP + row] = av.y;
            As[(lk + 2) * BMP + row] = av.z;
            As[(lk + 3) * BMP + row] = av.w;
            Bs[(lk + 0) * BMP + row] = bv.x;
            Bs[(lk + 1) * BMP + row] = bv.y;
            Bs[(lk + 2) * BMP + row] = bv.z;
            Bs[(lk + 3) * BMP + row] = bv.w;
        }
        __syncthreads();

        #pragma unroll 8
        for (int kk = 0; kk < BK; kk++) {
            float4 a0 = *(const float4*)&As[kk * BMP + ty * 4];
            float4 a1 = *(const float4*)&As[kk * BMP + 64 + ty * 4];
            float4 b0 = *(const float4*)&Bs[kk * BMP + tx * 4];
            float4 b1 = *(const float4*)&Bs[kk * BMP + 64 + tx * 4];
            float a[8] = {a0.x, a0.y, a0.z, a0.w, a1.x, a1.y, a1.z, a1.w};
            float b[8] = {b0.x, b0.y, b0.z, b0.w, b1.x, b1.y, b1.z, b1.w};
            #pragma unroll
            for (int i = 0; i < 8; i++)
                #pragma unroll
                for (int j = 0; j < 8; j++)
                    acc[i][j] = fmaf(a[i], b[j], acc[i][j]);
        }
        __syncthreads();
    }

    // ---- scale ----
    const float scale = *scale_p;
    #pragma unroll
    for (int i = 0; i < 8; i++)
        #pragma unroll
        for (int j = 0; j < 8; j++)
            acc[i][j] *= scale;

    // ---- row partials: reduce across the 16 tx lanes (same warp half) ----
    #pragma unroll
    for (int i = 0; i < 8; i++) {
        const int row_l = (i < 4) ? (ty * 4 + i) : (64 + ty * 4 + (i - 4));
        float m = -3.0e38f;
        #pragma unroll
        for (int j = 0; j < 8; j++) m = fmaxf(m, acc[i][j]);
        #pragma unroll
        for (int o = 8; o >= 1; o >>= 1)
            m = fmaxf(m, __shfl_xor_sync(0xffffffffu, m, o));
        float s = 0.0f;
        #pragma unroll
        for (int j = 0; j < 8; j++) s += __expf(acc[i][j] - m);
        #pragma unroll
        for (int o = 8; o >= 1; o >>= 1)
            s += __shfl_xor_sync(0xffffffffu, s, o);
        if (tx == 0) {
            const size_t row_g = (size_t)blockIdx.y * BM + row_l;
            g_rowPart[row_g * NTILE + blockIdx.x] = make_float2(m, s);
        }
    }

    // ---- col partials: per-thread over its 8 rows, then reduce across ty via smem ----
    __syncthreads();                 // done with As/Bs, reuse smem
    float2* cpart = reinterpret_cast<float2*>(smem);   // cpart[ty][col], 16x128

    #pragma unroll
    for (int j = 0; j < 8; j++) {
        const int col_l = (j < 4) ? (tx * 4 + j) : (64 + tx * 4 + (j - 4));
        float m = -3.0e38f;
        #pragma unroll
        for (int i = 0; i < 8; i++) m = fmaxf(m, acc[i][j]);
        float s = 0.0f;
        #pragma unroll
        for (int i = 0; i < 8; i++) s += __expf(acc[i][j] - m);
        cpart[ty * BN + col_l] = make_float2(m, s);
    }
    __syncthreads();

    if (tid < BN) {
        const int c = tid;
        float M = -3.0e38f;
        #pragma unroll
        for (int t = 0; t < 16; t++) M = fmaxf(M, cpart[t * BN + c].x);
        float S = 0.0f;
        #pragma unroll
        for (int t = 0; t < 16; t++) {
            float2 p = cpart[t * BN + c];
            S += p.y * __expf(p.x - M);
        }
        const size_t col_g = (size_t)blockIdx.x * BN + c;
        g_colPart[col_g * NTILE + blockIdx.y] = make_float2(M, S);
    }
}

// ---------------------------------------------------------------------------
// Stage 2: combine 128 partials per row/col, compute diag, emit contrib[r].
// Grid N, block 128.
// ---------------------------------------------------------------------------
__global__ void __launch_bounds__(128)
clip_finalize(const float* __restrict__ A,
              const float* __restrict__ B,
              const float* __restrict__ scale_p)
{
    __shared__ float red[128];
    const int r = blockIdx.x;
    const int t = threadIdx.x;

    // ---- row LSE ----
    float2 p = g_rowPart[(size_t)r * NTILE + t];
    red[t] = p.x;  __syncthreads();
    #pragma unroll
    for (int s = 64; s > 0; s >>= 1) {
        if (t < s) red[t] = fmaxf(red[t], red[t + s]);
        __syncthreads();
    }
    const float Mr = red[0];  __syncthreads();
    red[t] = p.y * __expf(p.x - Mr);  __syncthreads();
    #pragma unroll
    for (int s = 64; s > 0; s >>= 1) {
        if (t < s) red[t] += red[t + s];
        __syncthreads();
    }
    const float lse_r = Mr + __logf(red[0]);  __syncthreads();

    // ---- col LSE ----
    float2 q = g_colPart[(size_t)r * NTILE + t];
    red[t] = q.x;  __syncthreads();
    #pragma unroll
    for (int s = 64; s > 0; s >>= 1) {
        if (t < s) red[t] = fmaxf(red[t], red[t + s]);
        __syncthreads();
    }
    const float Mc = red[0];  __syncthreads();
    red[t] = q.y * __expf(q.x - Mc);  __syncthreads();
    #pragma unroll
    for (int s = 64; s > 0; s >>= 1) {
        if (t < s) red[t] += red[t + s];
        __syncthreads();
    }
    const float lse_c = Mc + __logf(red[0]);  __syncthreads();

    // ---- diag: dot(I_r, T_r) ----
    float d = 0.0f;
    #pragma unroll
    for (int k = t; k < DDIM; k += 128)
        d = fmaf(A[(size_t)r * DDIM + k], B[(size_t)r * DDIM + k], d);
    red[t] = d;  __syncthreads();
    #pragma unroll
    for (int s = 64; s > 0; s >>= 1) {
        if (t < s) red[t] += red[t + s];
        __syncthreads();
    }
    if (t == 0) {
        const float diag = (*scale_p) * red[0];
        g_contrib[r] = (lse_r - diag) + (lse_c - diag);
    }
}

// ---------------------------------------------------------------------------
// Stage 3: deterministic final reduction to the scalar loss.
// ---------------------------------------------------------------------------
__global__ void __launch_bounds__(256)
clip_reduce_final(float* __restrict__ out)
{
    __shared__ float red[256];
    const int t = threadIdx.x;
    float s = 0.0f;
    for (int r = t; r < N; r += 256) s += g_contrib[r];
    red[t] = s;  __syncthreads();
    #pragma unroll
    for (int k = 128; k > 0; k >>= 1) {
        if (t < k) red[t] += red[t + k];
        __syncthreads();
    }
    if (t == 0) out[0] = red[0] * (0.5f / (float)N);
}

// ---------------------------------------------------------------------------
extern "C" void kernel_launch(void* const* d_in, const int* in_sizes, int n_in,
                              void* d_out, int out_size)
{
    const float* img   = (const float*)d_in[0];
    const float* txt   = (const float*)d_in[1];
    const float* scale = (const float*)d_in[2];
    float* out = (float*)d_out;

    dim3 g1(NTILE, NTILE);
    clip_gemm_lse_part<<<g1, 256>>>(img, txt, scale);
    clip_finalize<<<N, 128>>>(img, txt, scale);
    clip_reduce_final<<<1, 256>>>(out);
}

// round 4
// speedup vs baseline: 4.1625x; 4.1625x over previous
#include <cuda_runtime.h>
#include <cuda_bf16.h>
#include <cstdint>

#define N_    16384
#define DDIM  512
#define BM    256
#define BN    128
#define BK    32
#define NIT   (DDIM / BK)      // 16
#define GXT   (N_ / BN)        // 128 tile-cols (text)
#define GYT   (N_ / BM)        // 64  tile-rows (image)

#define RSTRIDE 40             // padded row stride in bf16 elems (80 bytes)
#define A_BYTES (BM * RSTRIDE * 2)   // 20480
#define B_BYTES (BN * RSTRIDE * 2)   // 10240
#define STAGE_BYTES (A_BYTES + B_BYTES)   // 30720
#define NSTAGE 4
#define SMEM_TOTAL (NSTAGE * STAGE_BYTES) // 122880

// ---------------- device scratch ----------------
__device__ __align__(16) __nv_bfloat16 g_Abf[(size_t)N_ * DDIM];
__device__ __align__(16) __nv_bfloat16 g_Bbf[(size_t)N_ * DDIM];
__device__ float2 g_rowPart[(size_t)N_ * GXT];   // 16 MB
__device__ float2 g_colPart[(size_t)N_ * GYT];   // 8 MB
__device__ float  g_contrib[N_];

// ---------------- helpers ----------------
__device__ __forceinline__ uint32_t smem_u32(const void* p) {
    uint32_t a;
    asm("{ .reg .u64 t; cvta.to.shared.u64 t, %1; cvt.u32.u64 %0, t; }" : "=r"(a) : "l"(p));
    return a;
}
__device__ __forceinline__ void cp16(uint32_t sa, const void* g) {
    asm volatile("cp.async.cg.shared.global [%0], [%1], 16;" :: "r"(sa), "l"(g) : "memory");
}
__device__ __forceinline__ void ldm_x4(uint32_t* d, uint32_t addr) {
    asm volatile("ldmatrix.sync.aligned.m8n8.x4.shared.b16 {%0,%1,%2,%3}, [%4];"
                 : "=r"(d[0]), "=r"(d[1]), "=r"(d[2]), "=r"(d[3]) : "r"(addr));
}
__device__ __forceinline__ void mma_bf16(float* d, const uint32_t* a, uint32_t b0, uint32_t b1) {
    asm volatile("mma.sync.aligned.m16n8k16.row.col.f32.bf16.bf16.f32 "
                 "{%0,%1,%2,%3}, {%4,%5,%6,%7}, {%8,%9}, {%0,%1,%2,%3};"
                 : "+f"(d[0]), "+f"(d[1]), "+f"(d[2]), "+f"(d[3])
                 : "r"(a[0]), "r"(a[1]), "r"(a[2]), "r"(a[3]), "r"(b0), "r"(b1));
}

// ---------------------------------------------------------------------------
// Stage 0: fp32 -> bf16
// ---------------------------------------------------------------------------
__global__ void __launch_bounds__(256)
clip_convert(const float* __restrict__ A, const float* __restrict__ B)
{
    const float* src = blockIdx.y ? B : A;
    __nv_bfloat16* dst = blockIdx.y ? g_Bbf : g_Abf;
    size_t i = ((size_t)blockIdx.x * 256 + threadIdx.x) * 8;
    float4 a = *(const float4*)(src + i);
    float4 b = *(const float4*)(src + i + 4);
    __nv_bfloat162 p0 = __floats2bfloat162_rn(a.x, a.y);
    __nv_bfloat162 p1 = __floats2bfloat162_rn(a.z, a.w);
    __nv_bfloat162 p2 = __floats2bfloat162_rn(b.x, b.y);
    __nv_bfloat162 p3 = __floats2bfloat162_rn(b.z, b.w);
    uint4 u = make_uint4(*(uint32_t*)&p0, *(uint32_t*)&p1, *(uint32_t*)&p2, *(uint32_t*)&p3);
    *(uint4*)(dst + i) = u;
}

// ---------------------------------------------------------------------------
// Stage 1: bf16 mma.sync GEMM (256x128 CTA tile) + fused LSE partials
// ---------------------------------------------------------------------------
__device__ __forceinline__ void load_stage(const __nv_bfloat16* __restrict__ Ag,
                                           const __nv_bfloat16* __restrict__ Bg,
                                           int it, int stage, uint32_t sb, int tid)
{
    const uint32_t baseA = sb + stage * STAGE_BYTES;
    const uint32_t baseB = baseA + A_BYTES;
    const int kb = it * BK;
    #pragma unroll
    for (int j = 0; j < 4; j++) {               // A: 256 rows x 4 chunks(16B)
        int idx = tid + j * 256;
        int row = idx >> 2, c = idx & 3;
        cp16(baseA + row * (RSTRIDE * 2) + c * 16,
             Ag + (size_t)row * DDIM + kb + c * 8);
    }
    #pragma unroll
    for (int j = 0; j < 2; j++) {               // B: 128 rows x 4 chunks
        int idx = tid + j * 256;
        int row = idx >> 2, c = idx & 3;
        cp16(baseB + row * (RSTRIDE * 2) + c * 16,
             Bg + (size_t)row * DDIM + kb + c * 8);
    }
    asm volatile("cp.async.commit_group;" ::: "memory");
}

__global__ void __launch_bounds__(256)
clip_gemm_lse(const float* __restrict__ scale_p)
{
    extern __shared__ char smem[];
    const uint32_t sb = smem_u32(smem);
    const int tid  = threadIdx.x;
    const int wid  = tid >> 5;
    const int lane = tid & 31;
    const int gr   = lane >> 2;     // 0..7
    const int tc   = lane & 3;      // 0..3
    const int wm   = wid >> 1;      // 0..3 : m-warp (64 rows each)
    const int wn   = wid & 1;       // 0..1 : n-warp (64 cols each)

    const __nv_bfloat16* Ag = g_Abf + (size_t)blockIdx.y * BM * DDIM;
    const __nv_bfloat16* Bg = g_Bbf + (size_t)blockIdx.x * BN * DDIM;

    float acc[4][8][4];
    #pragma unroll
    for (int mi = 0; mi < 4; mi++)
        #pragma unroll
        for (int ni = 0; ni < 8; ni++)
            #pragma unroll
            for (int c = 0; c < 4; c++) acc[mi][ni][c] = 0.0f;

    // prefetch 3 stages
    load_stage(Ag, Bg, 0, 0, sb, tid);
    load_stage(Ag, Bg, 1, 1, sb, tid);
    load_stage(Ag, Bg, 2, 2, sb, tid);

    // ldmatrix lane addressing (identical pattern for A and B tiles)
    const int lrow = lane & 15;         // row within 16-row fragment
    const int lk   = (lane >> 4) * 16;  // +0 or +16 bytes (k halves)

    for (int it = 0; it < NIT; it++) {
        const int stage = it & 3;
        if (it < NIT - 3) asm volatile("cp.async.wait_group 2;" ::: "memory");
        else              asm volatile("cp.async.wait_group 0;" ::: "memory");
        __syncthreads();

        if (it + 3 < NIT) load_stage(Ag, Bg, it + 3, (it + 3) & 3, sb, tid);

        const uint32_t tA = sb + stage * STAGE_BYTES;
        const uint32_t tB = tA + A_BYTES;

        #pragma unroll
        for (int ks = 0; ks < 2; ks++) {
            uint32_t af[4][4], bf[4][4];
            #pragma unroll
            for (int mi = 0; mi < 4; mi++) {
                int r = wm * 64 + mi * 16 + lrow;
                ldm_x4(af[mi], tA + r * (RSTRIDE * 2) + ks * 32 + lk);
            }
            #pragma unroll
            for (int nj = 0; nj < 4; nj++) {
                int r = wn * 64 + nj * 16 + lrow;
                ldm_x4(bf[nj], tB + r * (RSTRIDE * 2) + ks * 32 + lk);
            }
            #pragma unroll
            for (int mi = 0; mi < 4; mi++)
                #pragma unroll
                for (int ni = 0; ni < 8; ni++) {
                    const int nj = ni >> 1, odd = ni & 1;
                    mma_bf16(acc[mi][ni], af[mi], bf[nj][odd], bf[nj][odd + 2]);
                }
        }
        __syncthreads();
    }

    // ---- epilogue ----
    const float scl = __ldg(scale_p);
    #pragma unroll
    for (int mi = 0; mi < 4; mi++)
        #pragma unroll
        for (int ni = 0; ni < 8; ni++)
            #pragma unroll
            for (int c = 0; c < 4; c++) acc[mi][ni][c] *= scl;

    float* s_row  = (float*)smem;        // [2][256]
    float* s_col  = s_row + 512;         // [4][128]
    float* s_rowM = s_col + 512;         // [256]
    float* s_colM = s_rowM + 256;        // [128]
    float* s_rsum = s_colM + 128;        // [2][256]
    float* s_csum = s_rsum + 512;        // [4][128]

    // pass 1: maxes
    // rows: thread covers 8 rows (mi x half), 16 elems each (ni x b)
    #pragma unroll
    for (int mi = 0; mi < 4; mi++)
        #pragma unroll
        for (int h = 0; h < 2; h++) {
            float m = -3.0e38f;
            #pragma unroll
            for (int ni = 0; ni < 8; ni++) {
                m = fmaxf(m, acc[mi][ni][h * 2]);
                m = fmaxf(m, acc[mi][ni][h * 2 + 1]);
            }
            m = fmaxf(m, __shfl_xor_sync(0xffffffffu, m, 1));
            m = fmaxf(m, __shfl_xor_sync(0xffffffffu, m, 2));
            if (tc == 0) {
                int row = wm * 64 + mi * 16 + h * 8 + gr;
                s_row[wn * 256 + row] = m;
            }
        }
    // cols: thread covers 16 cols (ni x b), 8 elems each (mi x half)
    #pragma unroll
    for (int ni = 0; ni < 8; ni++)
        #pragma unroll
        for (int b = 0; b < 2; b++) {
            float m = -3.0e38f;
            #pragma unroll
            for (int mi = 0; mi < 4; mi++) {
                m = fmaxf(m, acc[mi][ni][b]);
                m = fmaxf(m, acc[mi][ni][2 + b]);
            }
            m = fmaxf(m, __shfl_xor_sync(0xffffffffu, m, 4));
            m = fmaxf(m, __shfl_xor_sync(0xffffffffu, m, 8));
            m = fmaxf(m, __shfl_xor_sync(0xffffffffu, m, 16));
            if (gr == 0) {
                int col = wn * 64 + ni * 8 + tc * 2 + b;
                s_col[wm * 128 + col] = m;
            }
        }
    __syncthreads();
    if (tid < 256) s_rowM[tid] = fmaxf(s_row[tid], s_row[256 + tid]);
    if (tid < 128) {
        float m = fmaxf(fmaxf(s_col[tid], s_col[128 + tid]),
                        fmaxf(s_col[256 + tid], s_col[384 + tid]));
        s_colM[tid] = m;
    }
    __syncthreads();

    // pass 2: sums of exp
    float rM[8], cM[16];
    #pragma unroll
    for (int mi = 0; mi < 4; mi++)
        #pragma unroll
        for (int h = 0; h < 2; h++)
            rM[mi * 2 + h] = s_rowM[wm * 64 + mi * 16 + h * 8 + gr];
    #pragma unroll
    for (int ni = 0; ni < 8; ni++)
        #pragma unroll
        for (int b = 0; b < 2; b++)
            cM[ni * 2 + b] = s_colM[wn * 64 + ni * 8 + tc * 2 + b];

    float csum[16];
    #pragma unroll
    for (int k = 0; k < 16; k++) csum[k] = 0.0f;

    #pragma unroll
    for (int mi = 0; mi < 4; mi++)
        #pragma unroll
        for (int h = 0; h < 2; h++) {
            float rs = 0.0f;
            const float rm = rM[mi * 2 + h];
            #pragma unroll
            for (int ni = 0; ni < 8; ni++)
                #pragma unroll
                for (int b = 0; b < 2; b++) {
                    float v = acc[mi][ni][h * 2 + b];
                    rs += __expf(v - rm);
                    csum[ni * 2 + b] += __expf(v - cM[ni * 2 + b]);
                }
            rs += __shfl_xor_sync(0xffffffffu, rs, 1);
            rs += __shfl_xor_sync(0xffffffffu, rs, 2);
            if (tc == 0) {
                int row = wm * 64 + mi * 16 + h * 8 + gr;
                s_rsum[wn * 256 + row] = rs;
            }
        }
    #pragma unroll
    for (int ni = 0; ni < 8; ni++)
        #pragma unroll
        for (int b = 0; b < 2; b++) {
            float cs = csum[ni * 2 + b];
            cs += __shfl_xor_sync(0xffffffffu, cs, 4);
            cs += __shfl_xor_sync(0xffffffffu, cs, 8);
            cs += __shfl_xor_sync(0xffffffffu, cs, 16);
            if (gr == 0) {
                int col = wn * 64 + ni * 8 + tc * 2 + b;
                s_csum[wm * 128 + col] = cs;
            }
        }
    __syncthreads();

    if (tid < 256) {
        float2 rp = make_float2(s_rowM[tid], s_rsum[tid] + s_rsum[256 + tid]);
        g_rowPart[((size_t)blockIdx.y * BM + tid) * GXT + blockIdx.x] = rp;
    }
    if (tid < 128) {
        float cs = s_csum[tid] + s_csum[128 + tid] + s_csum[256 + tid] + s_csum[384 + tid];
        g_colPart[((size_t)blockIdx.x * BN + tid) * GYT + blockIdx.y] =
            make_float2(s_colM[tid], cs);
    }
}

// ---------------------------------------------------------------------------
// Stage 2: combine partials, fp32 diag
// ---------------------------------------------------------------------------
__global__ void __launch_bounds__(128)
clip_finalize(const float* __restrict__ A, const float* __restrict__ B,
              const float* __restrict__ scale_p)
{
    __shared__ float red[128];
    const int r = blockIdx.x;
    const int t = threadIdx.x;

    // row LSE: GXT=128 partials
    float2 p = g_rowPart[(size_t)r * GXT + t];
    red[t] = p.x;  __syncthreads();
    #pragma unroll
    for (int s = 64; s > 0; s >>= 1) { if (t < s) red[t] = fmaxf(red[t], red[t + s]); __syncthreads(); }
    const float Mr = red[0];  __syncthreads();
    red[t] = p.y * __expf(p.x - Mr);  __syncthreads();
    #pragma unroll
    for (int s = 64; s > 0; s >>= 1) { if (t < s) red[t] += red[t + s]; __syncthreads(); }
    const float lse_r = Mr + __logf(red[0]);  __syncthreads();

    // col LSE: GYT=64 partials
    float2 q = (t < GYT) ? g_colPart[(size_t)r * GYT + t] : make_float2(-3.0e38f, 0.0f);
    red[t] = q.x;  __syncthreads();
    #pragma unroll
    for (int s = 64; s > 0; s >>= 1) { if (t < s) red[t] = fmaxf(red[t], red[t + s]); __syncthreads(); }
    const float Mc = red[0];  __syncthreads();
    red[t] = q.y * __expf(q.x - Mc);  __syncthreads();
    #pragma unroll
    for (int s = 64; s > 0; s >>= 1) { if (t < s) red[t] += red[t + s]; __syncthreads(); }
    const float lse_c = Mc + __logf(red[0]);  __syncthreads();

    float d = 0.0f;
    #pragma unroll
    for (int k = t; k < DDIM; k += 128)
        d = fmaf(A[(size_t)r * DDIM + k], B[(size_t)r * DDIM + k], d);
    red[t] = d;  __syncthreads();
    #pragma unroll
    for (int s = 64; s > 0; s >>= 1) { if (t < s) red[t] += red[t + s]; __syncthreads(); }
    if (t == 0) {
        const float diag = (*scale_p) * red[0];
        g_contrib[r] = (lse_r - diag) + (lse_c - diag);
    }
}

__global__ void __launch_bounds__(256)
clip_reduce_final(float* __restrict__ out)
{
    __shared__ float red[256];
    const int t = threadIdx.x;
    float s = 0.0f;
    for (int r = t; r < N_; r += 256) s += g_contrib[r];
    red[t] = s;  __syncthreads();
    #pragma unroll
    for (int k = 128; k > 0; k >>= 1) { if (t < k) red[t] += red[t + k]; __syncthreads(); }
    if (t == 0) out[0] = red[0] * (0.5f / (float)N_);
}

// ---------------------------------------------------------------------------
extern "C" void kernel_launch(void* const* d_in, const int* in_sizes, int n_in,
                              void* d_out, int out_size)
{
    const float* img   = (const float*)d_in[0];
    const float* txt   = (const float*)d_in[1];
    const float* scale = (const float*)d_in[2];
    float* out = (float*)d_out;

    cudaFuncSetAttribute(clip_gemm_lse, cudaFuncAttributeMaxDynamicSharedMemorySize, SMEM_TOTAL);

    clip_convert<<<dim3((N_ * DDIM) / (256 * 8), 2), 256>>>(img, txt);
    clip_gemm_lse<<<dim3(GXT, GYT), 256, SMEM_TOTAL>>>(scale);
    clip_finalize<<<N_, 128>>>(img, txt, scale);
    clip_reduce_final<<<1, 256>>>(out);
}

// round 5
// speedup vs baseline: 4.4357x; 1.0656x over previous
#include <cuda_runtime.h>
#include <cuda_bf16.h>
#include <cstdint>

#define N_    16384
#define DDIM  512
#define BM    256
#define BN    128
#define BK    64               // fp8 elements per k-chunk (64 bytes)
#define NIT   (DDIM / BK)      // 8
#define GXT   (N_ / BN)        // 128 tile-cols (text)
#define GYT   (N_ / BM)        // 64  tile-rows (image)

#define RSTRB 80               // padded row stride in BYTES (64 data + 16 pad)
#define A_BYTES (BM * RSTRB)         // 20480
#define B_BYTES (BN * RSTRB)         // 10240
#define STAGE_BYTES (A_BYTES + B_BYTES)   // 30720
#define NSTAGE 4
#define SMEM_TOTAL (NSTAGE * STAGE_BYTES) // 122880

// ---------------- device scratch ----------------
__device__ __align__(16) uint8_t g_Af8[(size_t)N_ * DDIM];   // 8 MB e4m3
__device__ __align__(16) uint8_t g_Bf8[(size_t)N_ * DDIM];   // 8 MB e4m3
__device__ float2 g_rowPart[(size_t)N_ * GXT];   // 16 MB
__device__ float2 g_colPart[(size_t)N_ * GYT];   // 8 MB
__device__ float  g_contrib[N_];

// ---------------- helpers ----------------
__device__ __forceinline__ uint32_t smem_u32(const void* p) {
    uint32_t a;
    asm("{ .reg .u64 t; cvta.to.shared.u64 t, %1; cvt.u32.u64 %0, t; }" : "=r"(a) : "l"(p));
    return a;
}
__device__ __forceinline__ void cp16(uint32_t sa, const void* g) {
    asm volatile("cp.async.cg.shared.global [%0], [%1], 16;" :: "r"(sa), "l"(g) : "memory");
}
__device__ __forceinline__ void ldm_x4(uint32_t* d, uint32_t addr) {
    asm volatile("ldmatrix.sync.aligned.m8n8.x4.shared.b16 {%0,%1,%2,%3}, [%4];"
                 : "=r"(d[0]), "=r"(d[1]), "=r"(d[2]), "=r"(d[3]) : "r"(addr));
}
__device__ __forceinline__ void mma_fp8(float* d, const uint32_t* a, uint32_t b0, uint32_t b1) {
    asm volatile("mma.sync.aligned.m16n8k32.row.col.f32.e4m3.e4m3.f32 "
                 "{%0,%1,%2,%3}, {%4,%5,%6,%7}, {%8,%9}, {%0,%1,%2,%3};"
                 : "+f"(d[0]), "+f"(d[1]), "+f"(d[2]), "+f"(d[3])
                 : "r"(a[0]), "r"(a[1]), "r"(a[2]), "r"(a[3]), "r"(b0), "r"(b1));
}
__device__ __forceinline__ uint16_t f2e4m3x2(float lo, float hi) {
    uint16_t r;
    asm("cvt.rn.satfinite.e4m3x2.f32 %0, %1, %2;" : "=h"(r) : "f"(hi), "f"(lo));
    return r;
}

// ---------------------------------------------------------------------------
// Stage 0: fp32 -> e4m3   (each thread: 16 floats -> 16 bytes)
// ---------------------------------------------------------------------------
__global__ void __launch_bounds__(256)
clip_convert(const float* __restrict__ A, const float* __restrict__ B)
{
    const float* src = blockIdx.y ? B : A;
    uint8_t* dst = blockIdx.y ? g_Bf8 : g_Af8;
    size_t i = ((size_t)blockIdx.x * 256 + threadIdx.x) * 16;
    float4 v0 = *(const float4*)(src + i);
    float4 v1 = *(const float4*)(src + i + 4);
    float4 v2 = *(const float4*)(src + i + 8);
    float4 v3 = *(const float4*)(src + i + 12);
    uint16_t h[8];
    h[0] = f2e4m3x2(v0.x, v0.y);  h[1] = f2e4m3x2(v0.z, v0.w);
    h[2] = f2e4m3x2(v1.x, v1.y);  h[3] = f2e4m3x2(v1.z, v1.w);
    h[4] = f2e4m3x2(v2.x, v2.y);  h[5] = f2e4m3x2(v2.z, v2.w);
    h[6] = f2e4m3x2(v3.x, v3.y);  h[7] = f2e4m3x2(v3.z, v3.w);
    uint4 u;
    u.x = (uint32_t)h[0] | ((uint32_t)h[1] << 16);
    u.y = (uint32_t)h[2] | ((uint32_t)h[3] << 16);
    u.z = (uint32_t)h[4] | ((uint32_t)h[5] << 16);
    u.w = (uint32_t)h[6] | ((uint32_t)h[7] << 16);
    *(uint4*)(dst + i) = u;
}

// ---------------------------------------------------------------------------
// Stage 1: fp8 mma.sync GEMM (256x128 CTA tile) + fused LSE partials
// ---------------------------------------------------------------------------
__device__ __forceinline__ void load_stage(const uint8_t* __restrict__ Ag,
                                           const uint8_t* __restrict__ Bg,
                                           int it, int stage, uint32_t sb, int tid)
{
    const uint32_t baseA = sb + stage * STAGE_BYTES;
    const uint32_t baseB = baseA + A_BYTES;
    const int kb = it * BK;                      // byte offset in K
    #pragma unroll
    for (int j = 0; j < 4; j++) {                // A: 256 rows x 4 chunks(16B)
        int idx = tid + j * 256;
        int row = idx >> 2, c = idx & 3;
        cp16(baseA + row * RSTRB + c * 16,
             Ag + (size_t)row * DDIM + kb + c * 16);
    }
    #pragma unroll
    for (int j = 0; j < 2; j++) {                // B: 128 rows x 4 chunks
        int idx = tid + j * 256;
        int row = idx >> 2, c = idx & 3;
        cp16(baseB + row * RSTRB + c * 16,
             Bg + (size_t)row * DDIM + kb + c * 16);
    }
    asm volatile("cp.async.commit_group;" ::: "memory");
}

__global__ void __launch_bounds__(256)
clip_gemm_lse(const float* __restrict__ scale_p)
{
    extern __shared__ char smem[];
    const uint32_t sb = smem_u32(smem);
    const int tid  = threadIdx.x;
    const int wid  = tid >> 5;
    const int lane = tid & 31;
    const int gr   = lane >> 2;     // 0..7
    const int tc   = lane & 3;      // 0..3
    const int wm   = wid >> 1;      // 0..3 : m-warp (64 rows each)
    const int wn   = wid & 1;       // 0..1 : n-warp (64 cols each)

    const uint8_t* Ag = g_Af8 + (size_t)blockIdx.y * BM * DDIM;
    const uint8_t* Bg = g_Bf8 + (size_t)blockIdx.x * BN * DDIM;

    float acc[4][8][4];
    #pragma unroll
    for (int mi = 0; mi < 4; mi++)
        #pragma unroll
        for (int ni = 0; ni < 8; ni++)
            #pragma unroll
            for (int c = 0; c < 4; c++) acc[mi][ni][c] = 0.0f;

    load_stage(Ag, Bg, 0, 0, sb, tid);
    load_stage(Ag, Bg, 1, 1, sb, tid);
    load_stage(Ag, Bg, 2, 2, sb, tid);

    // ldmatrix lane addressing: row = lane&15 (32B k-rows), +16B half by lane>>4
    const int lrow = lane & 15;
    const int lk   = (lane >> 4) * 16;

    for (int it = 0; it < NIT; it++) {
        const int stage = it & 3;
        if (it < NIT - 3) asm volatile("cp.async.wait_group 2;" ::: "memory");
        else              asm volatile("cp.async.wait_group 0;" ::: "memory");
        __syncthreads();

        if (it + 3 < NIT) load_stage(Ag, Bg, it + 3, (it + 3) & 3, sb, tid);

        const uint32_t tA = sb + stage * STAGE_BYTES;
        const uint32_t tB = tA + A_BYTES;

        #pragma unroll
        for (int ks = 0; ks < 2; ks++) {         // two k32 steps per 64B chunk
            uint32_t af[4][4], bf[4][4];
            #pragma unroll
            for (int mi = 0; mi < 4; mi++) {
                int r = wm * 64 + mi * 16 + lrow;
                ldm_x4(af[mi], tA + r * RSTRB + ks * 32 + lk);
            }
            #pragma unroll
            for (int nj = 0; nj < 4; nj++) {
                int r = wn * 64 + nj * 16 + lrow;
                ldm_x4(bf[nj], tB + r * RSTRB + ks * 32 + lk);
            }
            #pragma unroll
            for (int mi = 0; mi < 4; mi++)
                #pragma unroll
                for (int ni = 0; ni < 8; ni++) {
                    const int nj = ni >> 1, odd = ni & 1;
                    mma_fp8(acc[mi][ni], af[mi], bf[nj][odd], bf[nj][odd + 2]);
                }
        }
        __syncthreads();
    }

    // ---- epilogue (identical to verified R4) ----
    const float scl = __ldg(scale_p);
    #pragma unroll
    for (int mi = 0; mi < 4; mi++)
        #pragma unroll
        for (int ni = 0; ni < 8; ni++)
            #pragma unroll
            for (int c = 0; c < 4; c++) acc[mi][ni][c] *= scl;

    float* s_row  = (float*)smem;        // [2][256]
    float* s_col  = s_row + 512;         // [4][128]
    float* s_rowM = s_col + 512;         // [256]
    float* s_colM = s_rowM + 256;        // [128]
    float* s_rsum = s_colM + 128;        // [2][256]
    float* s_csum = s_rsum + 512;        // [4][128]

    #pragma unroll
    for (int mi = 0; mi < 4; mi++)
        #pragma unroll
        for (int h = 0; h < 2; h++) {
            float m = -3.0e38f;
            #pragma unroll
            for (int ni = 0; ni < 8; ni++) {
                m = fmaxf(m, acc[mi][ni][h * 2]);
                m = fmaxf(m, acc[mi][ni][h * 2 + 1]);
            }
            m = fmaxf(m, __shfl_xor_sync(0xffffffffu, m, 1));
            m = fmaxf(m, __shfl_xor_sync(0xffffffffu, m, 2));
            if (tc == 0) {
                int row = wm * 64 + mi * 16 + h * 8 + gr;
                s_row[wn * 256 + row] = m;
            }
        }
    #pragma unroll
    for (int ni = 0; ni < 8; ni++)
        #pragma unroll
        for (int b = 0; b < 2; b++) {
            float m = -3.0e38f;
            #pragma unroll
            for (int mi = 0; mi < 4; mi++) {
                m = fmaxf(m, acc[mi][ni][b]);
                m = fmaxf(m, acc[mi][ni][2 + b]);
            }
            m = fmaxf(m, __shfl_xor_sync(0xffffffffu, m, 4));
            m = fmaxf(m, __shfl_xor_sync(0xffffffffu, m, 8));
            m = fmaxf(m, __shfl_xor_sync(0xffffffffu, m, 16));
            if (gr == 0) {
                int col = wn * 64 + ni * 8 + tc * 2 + b;
                s_col[wm * 128 + col] = m;
            }
        }
    __syncthreads();
    if (tid < 256) s_rowM[tid] = fmaxf(s_row[tid], s_row[256 + tid]);
    if (tid < 128) {
        float m = fmaxf(fmaxf(s_col[tid], s_col[128 + tid]),
                        fmaxf(s_col[256 + tid], s_col[384 + tid]));
        s_colM[tid] = m;
    }
    __syncthreads();

    float rM[8], cM[16];
    #pragma unroll
    for (int mi = 0; mi < 4; mi++)
        #pragma unroll
        for (int h = 0; h < 2; h++)
            rM[mi * 2 + h] = s_rowM[wm * 64 + mi * 16 + h * 8 + gr];
    #pragma unroll
    for (int ni = 0; ni < 8; ni++)
        #pragma unroll
        for (int b = 0; b < 2; b++)
            cM[ni * 2 + b] = s_colM[wn * 64 + ni * 8 + tc * 2 + b];

    float csum[16];
    #pragma unroll
    for (int k = 0; k < 16; k++) csum[k] = 0.0f;

    #pragma unroll
    for (int mi = 0; mi < 4; mi++)
        #pragma unroll
        for (int h = 0; h < 2; h++) {
            float rs = 0.0f;
            const float rm = rM[mi * 2 + h];
            #pragma unroll
            for (int ni = 0; ni < 8; ni++)
                #pragma unroll
                for (int b = 0; b < 2; b++) {
                    float v = acc[mi][ni][h * 2 + b];
                    rs += __expf(v - rm);
                    csum[ni * 2 + b] += __expf(v - cM[ni * 2 + b]);
                }
            rs += __shfl_xor_sync(0xffffffffu, rs, 1);
            rs += __shfl_xor_sync(0xffffffffu, rs, 2);
            if (tc == 0) {
                int row = wm * 64 + mi * 16 + h * 8 + gr;
                s_rsum[wn * 256 + row] = rs;
            }
        }
    #pragma unroll
    for (int ni = 0; ni < 8; ni++)
        #pragma unroll
        for (int b = 0; b < 2; b++) {
            float cs = csum[ni * 2 + b];
            cs += __shfl_xor_sync(0xffffffffu, cs, 4);
            cs += __shfl_xor_sync(0xffffffffu, cs, 8);
            cs += __shfl_xor_sync(0xffffffffu, cs, 16);
            if (gr == 0) {
                int col = wn * 64 + ni * 8 + tc * 2 + b;
                s_csum[wm * 128 + col] = cs;
            }
        }
    __syncthreads();

    if (tid < 256) {
        float2 rp = make_float2(s_rowM[tid], s_rsum[tid] + s_rsum[256 + tid]);
        g_rowPart[((size_t)blockIdx.y * BM + tid) * GXT + blockIdx.x] = rp;
    }
    if (tid < 128) {
        float cs = s_csum[tid] + s_csum[128 + tid] + s_csum[256 + tid] + s_csum[384 + tid];
        g_colPart[((size_t)blockIdx.x * BN + tid) * GYT + blockIdx.y] =
            make_float2(s_colM[tid], cs);
    }
}

// ---------------------------------------------------------------------------
// Stage 2: combine partials, fp32 diag
// ---------------------------------------------------------------------------
__global__ void __launch_bounds__(128)
clip_finalize(const float* __restrict__ A, const float* __restrict__ B,
              const float* __restrict__ scale_p)
{
    __shared__ float red[128];
    const int r = blockIdx.x;
    const int t = threadIdx.x;

    float2 p = g_rowPart[(size_t)r * GXT + t];
    red[t] = p.x;  __syncthreads();
    #pragma unroll
    for (int s = 64; s > 0; s >>= 1) { if (t < s) red[t] = fmaxf(red[t], red[t + s]); __syncthreads(); }
    const float Mr = red[0];  __syncthreads();
    red[t] = p.y * __expf(p.x - Mr);  __syncthreads();
    #pragma unroll
    for (int s = 64; s > 0; s >>= 1) { if (t < s) red[t] += red[t + s]; __syncthreads(); }
    const float lse_r = Mr + __logf(red[0]);  __syncthreads();

    float2 q = (t < GYT) ? g_colPart[(size_t)r * GYT + t] : make_float2(-3.0e38f, 0.0f);
    red[t] = q.x;  __syncthreads();
    #pragma unroll
    for (int s = 64; s > 0; s >>= 1) { if (t < s) red[t] = fmaxf(red[t], red[t + s]); __syncthreads(); }
    const float Mc = red[0];  __syncthreads();
    red[t] = q.y * __expf(q.x - Mc);  __syncthreads();
    #pragma unroll
    for (int s = 64; s > 0; s >>= 1) { if (t < s) red[t] += red[t + s]; __syncthreads(); }
    const float lse_c = Mc + __logf(red[0]);  __syncthreads();

    float d = 0.0f;
    #pragma unroll
    for (int k = t; k < DDIM; k += 128)
        d = fmaf(A[(size_t)r * DDIM + k], B[(size_t)r * DDIM + k], d);
    red[t] = d;  __syncthreads();
    #pragma unroll
    for (int s = 64; s > 0; s >>= 1) { if (t < s) red[t] += red[t + s]; __syncthreads(); }
    if (t == 0) {
        const float diag = (*scale_p) * red[0];
        g_contrib[r] = (lse_r - diag) + (lse_c - diag);
    }
}

__global__ void __launch_bounds__(256)
clip_reduce_final(float* __restrict__ out)
{
    __shared__ float red[256];
    const int t = threadIdx.x;
    float s = 0.0f;
    for (int r = t; r < N_; r += 256) s += g_contrib[r];
    red[t] = s;  __syncthreads();
    #pragma unroll
    for (int k = 128; k > 0; k >>= 1) { if (t < k) red[t] += red[t + k]; __syncthreads(); }
    if (t == 0) out[0] = red[0] * (0.5f / (float)N_);
}

// ---------------------------------------------------------------------------
extern "C" void kernel_launch(void* const* d_in, const int* in_sizes, int n_in,
                              void* d_out, int out_size)
{
    const float* img   = (const float*)d_in[0];
    const float* txt   = (const float*)d_in[1];
    const float* scale = (const float*)d_in[2];
    float* out = (float*)d_out;

    cudaFuncSetAttribute(clip_gemm_lse, cudaFuncAttributeMaxDynamicSharedMemorySize, SMEM_TOTAL);

    clip_convert<<<dim3((N_ * DDIM) / (256 * 16), 2), 256>>>(img, txt);
    clip_gemm_lse<<<dim3(GXT, GYT), 256, SMEM_TOTAL>>>(scale);
    clip_finalize<<<N_, 128>>>(img, txt, scale);
    clip_reduce_final<<<1, 256>>>(out);
}

// round 6
// speedup vs baseline: 4.9734x; 1.1212x over previous
#include <cuda_runtime.h>
#include <cuda_bf16.h>
#include <cstdint>

#define N_    16384
#define DDIM  512
#define BM    128
#define BN    128
#define BK    32               // bf16 elems per k-chunk (64 B)
#define NIT   (DDIM / BK)      // 16
#define GT    (N_ / 128)       // 128 tiles per dim

#define RSTRB 80               // padded row stride bytes (64 data + 16 pad)
#define A_BYTES (BM * RSTRB)         // 10240
#define STAGE_BYTES (2 * A_BYTES)    // 20480 (A + B)
#define NSTAGE 4
#define SMEM_TOTAL (NSTAGE * STAGE_BYTES) // 81920

#define LOG2E 1.44269504088896f
#define LN2   0.69314718055995f

// ---------------- device scratch ----------------
__device__ __align__(16) __nv_bfloat16 g_Abf[(size_t)N_ * DDIM];
__device__ __align__(16) __nv_bfloat16 g_Bbf[(size_t)N_ * DDIM];
__device__ float2 g_rowPart[(size_t)N_ * GT];    // 16 MB  (log2-domain partials)
__device__ float2 g_colPart[(size_t)N_ * GT];    // 16 MB
__device__ float  g_contrib[N_];

// ---------------- helpers ----------------
__device__ __forceinline__ uint32_t smem_u32(const void* p) {
    uint32_t a;
    asm("{ .reg .u64 t; cvta.to.shared.u64 t, %1; cvt.u32.u64 %0, t; }" : "=r"(a) : "l"(p));
    return a;
}
__device__ __forceinline__ void cp16(uint32_t sa, const void* g) {
    asm volatile("cp.async.cg.shared.global [%0], [%1], 16;" :: "r"(sa), "l"(g) : "memory");
}
__device__ __forceinline__ void ldm_x4(uint32_t* d, uint32_t addr) {
    asm volatile("ldmatrix.sync.aligned.m8n8.x4.shared.b16 {%0,%1,%2,%3}, [%4];"
                 : "=r"(d[0]), "=r"(d[1]), "=r"(d[2]), "=r"(d[3]) : "r"(addr));
}
__device__ __forceinline__ void mma_bf16(float* d, const uint32_t* a, uint32_t b0, uint32_t b1) {
    asm volatile("mma.sync.aligned.m16n8k16.row.col.f32.bf16.bf16.f32 "
                 "{%0,%1,%2,%3}, {%4,%5,%6,%7}, {%8,%9}, {%0,%1,%2,%3};"
                 : "+f"(d[0]), "+f"(d[1]), "+f"(d[2]), "+f"(d[3])
                 : "r"(a[0]), "r"(a[1]), "r"(a[2]), "r"(a[3]), "r"(b0), "r"(b1));
}
__device__ __forceinline__ float ex2f(float x) {
    float r; asm("ex2.approx.ftz.f32 %0, %1;" : "=f"(r) : "f"(x)); return r;
}
__device__ __forceinline__ float lg2f(float x) {
    float r; asm("lg2.approx.f32 %0, %1;" : "=f"(r) : "f"(x)); return r;
}

// ---------------------------------------------------------------------------
// Stage 0: fp32 -> bf16
// ---------------------------------------------------------------------------
__global__ void __launch_bounds__(256)
clip_convert(const float* __restrict__ A, const float* __restrict__ B)
{
    const float* src = blockIdx.y ? B : A;
    __nv_bfloat16* dst = blockIdx.y ? g_Bbf : g_Abf;
    size_t i = ((size_t)blockIdx.x * 256 + threadIdx.x) * 8;
    float4 a = *(const float4*)(src + i);
    float4 b = *(const float4*)(src + i + 4);
    __nv_bfloat162 p0 = __floats2bfloat162_rn(a.x, a.y);
    __nv_bfloat162 p1 = __floats2bfloat162_rn(a.z, a.w);
    __nv_bfloat162 p2 = __floats2bfloat162_rn(b.x, b.y);
    __nv_bfloat162 p3 = __floats2bfloat162_rn(b.z, b.w);
    uint4 u = make_uint4(*(uint32_t*)&p0, *(uint32_t*)&p1, *(uint32_t*)&p2, *(uint32_t*)&p3);
    *(uint4*)(dst + i) = u;
}

// ---------------------------------------------------------------------------
// Stage 1: bf16 mma.sync GEMM (128x128 tile, 2 CTAs/SM) + fused log2-LSE
// ---------------------------------------------------------------------------
__device__ __forceinline__ void load_stage(const __nv_bfloat16* __restrict__ Ag,
                                           const __nv_bfloat16* __restrict__ Bg,
                                           int it, int stage, uint32_t sb, int tid)
{
    const uint32_t baseA = sb + stage * STAGE_BYTES;
    const uint32_t baseB = baseA + A_BYTES;
    const int kb = it * BK;
    #pragma unroll
    for (int j = 0; j < 2; j++) {               // A: 128 rows x 4 chunks(16B)
        int idx = tid + j * 256;
        int row = idx >> 2, c = idx & 3;
        cp16(baseA + row * RSTRB + c * 16,
             Ag + (size_t)row * DDIM + kb + c * 8);
    }
    #pragma unroll
    for (int j = 0; j < 2; j++) {               // B: 128 rows x 4 chunks
        int idx = tid + j * 256;
        int row = idx >> 2, c = idx & 3;
        cp16(baseB + row * RSTRB + c * 16,
             Bg + (size_t)row * DDIM + kb + c * 8);
    }
    asm volatile("cp.async.commit_group;" ::: "memory");
}

__global__ void __launch_bounds__(256, 2)
clip_gemm_lse(const float* __restrict__ scale_p)
{
    extern __shared__ char smem[];
    const uint32_t sb = smem_u32(smem);
    const int tid  = threadIdx.x;
    const int wid  = tid >> 5;
    const int lane = tid & 31;
    const int gr   = lane >> 2;     // 0..7
    const int tc   = lane & 3;      // 0..3
    const int wm   = wid >> 2;      // 0..1 : 64-row block
    const int wn   = wid & 3;       // 0..3 : 32-col block

    const __nv_bfloat16* Ag = g_Abf + (size_t)blockIdx.y * BM * DDIM;
    const __nv_bfloat16* Bg = g_Bbf + (size_t)blockIdx.x * BN * DDIM;

    float acc[4][4][4];
    #pragma unroll
    for (int mi = 0; mi < 4; mi++)
        #pragma unroll
        for (int ni = 0; ni < 4; ni++)
            #pragma unroll
            for (int c = 0; c < 4; c++) acc[mi][ni][c] = 0.0f;

    load_stage(Ag, Bg, 0, 0, sb, tid);
    load_stage(Ag, Bg, 1, 1, sb, tid);
    load_stage(Ag, Bg, 2, 2, sb, tid);

    const int lrow = lane & 15;
    const int lk   = (lane >> 4) * 16;

    for (int it = 0; it < NIT; it++) {
        const int stage = it & 3;
        if (it < NIT - 3) asm volatile("cp.async.wait_group 2;" ::: "memory");
        else              asm volatile("cp.async.wait_group 0;" ::: "memory");
        __syncthreads();

        if (it + 3 < NIT) load_stage(Ag, Bg, it + 3, (it + 3) & 3, sb, tid);

        const uint32_t tA = sb + stage * STAGE_BYTES;
        const uint32_t tB = tA + A_BYTES;

        #pragma unroll
        for (int ks = 0; ks < 2; ks++) {        // two k16 steps per 32-elem chunk
            uint32_t af[4][4], bf[2][4];
            #pragma unroll
            for (int mi = 0; mi < 4; mi++) {
                int r = wm * 64 + mi * 16 + lrow;
                ldm_x4(af[mi], tA + r * RSTRB + ks * 32 + lk);
            }
            #pragma unroll
            for (int nj = 0; nj < 2; nj++) {
                int r = wn * 32 + nj * 16 + lrow;
                ldm_x4(bf[nj], tB + r * RSTRB + ks * 32 + lk);
            }
            #pragma unroll
            for (int mi = 0; mi < 4; mi++)
                #pragma unroll
                for (int ni = 0; ni < 4; ni++) {
                    const int nj = ni >> 1, odd = ni & 1;
                    mma_bf16(acc[mi][ni], af[mi], bf[nj][odd], bf[nj][odd + 2]);
                }
        }
        __syncthreads();
    }

    // ---- epilogue: log2-domain LSE partials ----
    const float w = __ldg(scale_p) * LOG2E;     // logits in log2 units
    #pragma unroll
    for (int mi = 0; mi < 4; mi++)
        #pragma unroll
        for (int ni = 0; ni < 4; ni++)
            #pragma unroll
            for (int c = 0; c < 4; c++) acc[mi][ni][c] *= w;

    float* s_row  = (float*)smem;        // [4][128] per n-warp row max
    float* s_col  = s_row + 512;         // [2][128] per m-warp col max
    float* s_rowM = s_col + 256;         // [128]
    float* s_colM = s_rowM + 128;        // [128]
    float* s_rsum = s_colM + 128;        // [4][128]
    float* s_csum = s_rsum + 512;        // [2][128]

    // pass 1: maxes.  thread rows: wm*64+mi*16+h*8+gr; cols: wn*32+ni*8+tc*2+b
    #pragma unroll
    for (int mi = 0; mi < 4; mi++)
        #pragma unroll
        for (int h = 0; h < 2; h++) {
            float m = -3.0e38f;
            #pragma unroll
            for (int ni = 0; ni < 4; ni++) {
                m = fmaxf(m, acc[mi][ni][h * 2]);
                m = fmaxf(m, acc[mi][ni][h * 2 + 1]);
            }
            m = fmaxf(m, __shfl_xor_sync(0xffffffffu, m, 1));
            m = fmaxf(m, __shfl_xor_sync(0xffffffffu, m, 2));
            if (tc == 0)
                s_row[wn * 128 + wm * 64 + mi * 16 + h * 8 + gr] = m;
        }
    #pragma unroll
    for (int ni = 0; ni < 4; ni++)
        #pragma unroll
        for (int b = 0; b < 2; b++) {
            float m = -3.0e38f;
            #pragma unroll
            for (int mi = 0; mi < 4; mi++) {
                m = fmaxf(m, acc[mi][ni][b]);
                m = fmaxf(m, acc[mi][ni][2 + b]);
            }
            m = fmaxf(m, __shfl_xor_sync(0xffffffffu, m, 4));
            m = fmaxf(m, __shfl_xor_sync(0xffffffffu, m, 8));
            m = fmaxf(m, __shfl_xor_sync(0xffffffffu, m, 16));
            if (gr == 0)
                s_col[wm * 128 + wn * 32 + ni * 8 + tc * 2 + b] = m;
        }
    __syncthreads();
    if (tid < 128) {
        s_rowM[tid] = fmaxf(fmaxf(s_row[tid], s_row[128 + tid]),
                            fmaxf(s_row[256 + tid], s_row[384 + tid]));
    } else {
        int c = tid - 128;
        s_colM[c] = fmaxf(s_col[c], s_col[128 + c]);
    }
    __syncthreads();

    // pass 2: 2^(v-m) sums
    float rM[8], cM[8];
    #pragma unroll
    for (int mi = 0; mi < 4; mi++)
        #pragma unroll
        for (int h = 0; h < 2; h++)
            rM[mi * 2 + h] = s_rowM[wm * 64 + mi * 16 + h * 8 + gr];
    #pragma unroll
    for (int ni = 0; ni < 4; ni++)
        #pragma unroll
        for (int b = 0; b < 2; b++)
            cM[ni * 2 + b] = s_colM[wn * 32 + ni * 8 + tc * 2 + b];

    float csum[8];
    #pragma unroll
    for (int k = 0; k < 8; k++) csum[k] = 0.0f;

    #pragma unroll
    for (int mi = 0; mi < 4; mi++)
        #pragma unroll
        for (int h = 0; h < 2; h++) {
            float rs = 0.0f;
            const float rm = rM[mi * 2 + h];
            #pragma unroll
            for (int ni = 0; ni < 4; ni++)
                #pragma unroll
                for (int b = 0; b < 2; b++) {
                    float v = acc[mi][ni][h * 2 + b];
                    rs += ex2f(v - rm);
                    csum[ni * 2 + b] += ex2f(v - cM[ni * 2 + b]);
                }
            rs += __shfl_xor_sync(0xffffffffu, rs, 1);
            rs += __shfl_xor_sync(0xffffffffu, rs, 2);
            if (tc == 0)
                s_rsum[wn * 128 + wm * 64 + mi * 16 + h * 8 + gr] = rs;
        }
    #pragma unroll
    for (int ni = 0; ni < 4; ni++)
        #pragma unroll
        for (int b = 0; b < 2; b++) {
            float cs = csum[ni * 2 + b];
            cs += __shfl_xor_sync(0xffffffffu, cs, 4);
            cs += __shfl_xor_sync(0xffffffffu, cs, 8);
            cs += __shfl_xor_sync(0xffffffffu, cs, 16);
            if (gr == 0)
                s_csum[wm * 128 + wn * 32 + ni * 8 + tc * 2 + b] = cs;
        }
    __syncthreads();

    if (tid < 128) {
        float rsum = s_rsum[tid] + s_rsum[128 + tid] + s_rsum[256 + tid] + s_rsum[384 + tid];
        g_rowPart[((size_t)blockIdx.y * BM + tid) * GT + blockIdx.x] =
            make_float2(s_rowM[tid], rsum);
    } else {
        int c = tid - 128;
        float cs = s_csum[c] + s_csum[128 + c];
        g_colPart[((size_t)blockIdx.x * BN + c) * GT + blockIdx.y] =
            make_float2(s_colM[c], cs);
    }
}

// ---------------------------------------------------------------------------
// Stage 2: combine 128 log2-domain partials per row/col, fp32 diag
// ---------------------------------------------------------------------------
__global__ void __launch_bounds__(128)
clip_finalize(const float* __restrict__ A, const float* __restrict__ B,
              const float* __restrict__ scale_p)
{
    __shared__ float red[128];
    const int r = blockIdx.x;
    const int t = threadIdx.x;

    float2 p = g_rowPart[(size_t)r * GT + t];
    red[t] = p.x;  __syncthreads();
    #pragma unroll
    for (int s = 64; s > 0; s >>= 1) { if (t < s) red[t] = fmaxf(red[t], red[t + s]); __syncthreads(); }
    const float Mr = red[0];  __syncthreads();
    red[t] = p.y * ex2f(p.x - Mr);  __syncthreads();
    #pragma unroll
    for (int s = 64; s > 0; s >>= 1) { if (t < s) red[t] += red[t + s]; __syncthreads(); }
    const float lse_r = LN2 * (Mr + lg2f(red[0]));  __syncthreads();

    float2 q = g_colPart[(size_t)r * GT + t];
    red[t] = q.x;  __syncthreads();
    #pragma unroll
    for (int s = 64; s > 0; s >>= 1) { if (t < s) red[t] = fmaxf(red[t], red[t + s]); __syncthreads(); }
    const float Mc = red[0];  __syncthreads();
    red[t] = q.y * ex2f(q.x - Mc);  __syncthreads();
    #pragma unroll
    for (int s = 64; s > 0; s >>= 1) { if (t < s) red[t] += red[t + s]; __syncthreads(); }
    const float lse_c = LN2 * (Mc + lg2f(red[0]));  __syncthreads();

    float d = 0.0f;
    #pragma unroll
    for (int k = t; k < DDIM; k += 128)
        d = fmaf(A[(size_t)r * DDIM + k], B[(size_t)r * DDIM + k], d);
    red[t] = d;  __syncthreads();
    #pragma unroll
    for (int s = 64; s > 0; s >>= 1) { if (t < s) red[t] += red[t + s]; __syncthreads(); }
    if (t == 0) {
        const float diag = (*scale_p) * red[0];
        g_contrib[r] = (lse_r - diag) + (lse_c - diag);
    }
}

__global__ void __launch_bounds__(256)
clip_reduce_final(float* __restrict__ out)
{
    __shared__ float red[256];
    const int t = threadIdx.x;
    float s = 0.0f;
    for (int r = t; r < N_; r += 256) s += g_contrib[r];
    red[t] = s;  __syncthreads();
    #pragma unroll
    for (int k = 128; k > 0; k >>= 1) { if (t < k) red[t] += red[t + k]; __syncthreads(); }
    if (t == 0) out[0] = red[0] * (0.5f / (float)N_);
}

// ---------------------------------------------------------------------------
extern "C" void kernel_launch(void* const* d_in, const int* in_sizes, int n_in,
                              void* d_out, int out_size)
{
    const float* img   = (const float*)d_in[0];
    const float* txt   = (const float*)d_in[1];
    const float* scale = (const float*)d_in[2];
    float* out = (float*)d_out;

    cudaFuncSetAttribute(clip_gemm_lse, cudaFuncAttributeMaxDynamicSharedMemorySize, SMEM_TOTAL);

    clip_convert<<<dim3((N_ * DDIM) / (256 * 8), 2), 256>>>(img, txt);
    clip_gemm_lse<<<dim3(GT, GT), 256, SMEM_TOTAL>>>(scale);
    clip_finalize<<<N_, 128>>>(img, txt, scale);
    clip_reduce_final<<<1, 256>>>(out);
}

// round 7
// speedup vs baseline: 8.8992x; 1.7894x over previous
#include <cuda_runtime.h>
#include <cuda_bf16.h>
#include <cstdint>

#define N_    16384
#define DDIM  512
#define BM    128
#define BN    128
#define BK    64               // int8 elems per k-chunk (64 B)
#define NIT   (DDIM / BK)      // 8
#define GT    (N_ / 128)       // 128 tiles per dim

#define RSTRB 80               // padded row stride bytes (64 data + 16 pad)
#define A_BYTES (BM * RSTRB)         // 10240
#define STAGE_BYTES (2 * A_BYTES)    // 20480
#define NSTAGE 4
#define SMEM_TOTAL (NSTAGE * STAGE_BYTES) // 81920

#define LOG2E 1.44269504088896f
#define LN2   0.69314718055995f

// ---------------- device scratch ----------------
__device__ __align__(16) int8_t g_Aq[(size_t)N_ * DDIM];   // 8 MB
__device__ __align__(16) int8_t g_Bq[(size_t)N_ * DDIM];   // 8 MB
__device__ float  g_sA[N_];
__device__ float  g_sB[N_];
__device__ float2 g_rowPart[(size_t)N_ * GT];    // 16 MB (log2-domain)
__device__ float2 g_colPart[(size_t)N_ * GT];    // 16 MB
__device__ float  g_contrib[N_];

// ---------------- helpers ----------------
__device__ __forceinline__ uint32_t smem_u32(const void* p) {
    uint32_t a;
    asm("{ .reg .u64 t; cvta.to.shared.u64 t, %1; cvt.u32.u64 %0, t; }" : "=r"(a) : "l"(p));
    return a;
}
__device__ __forceinline__ void cp16(uint32_t sa, const void* g) {
    asm volatile("cp.async.cg.shared.global [%0], [%1], 16;" :: "r"(sa), "l"(g) : "memory");
}
__device__ __forceinline__ void ldm_x4(uint32_t* d, uint32_t addr) {
    asm volatile("ldmatrix.sync.aligned.m8n8.x4.shared.b16 {%0,%1,%2,%3}, [%4];"
                 : "=r"(d[0]), "=r"(d[1]), "=r"(d[2]), "=r"(d[3]) : "r"(addr));
}
__device__ __forceinline__ void mma_s8(int* d, const uint32_t* a, uint32_t b0, uint32_t b1) {
    asm volatile("mma.sync.aligned.m16n8k32.row.col.s32.s8.s8.s32 "
                 "{%0,%1,%2,%3}, {%4,%5,%6,%7}, {%8,%9}, {%0,%1,%2,%3};"
                 : "+r"(d[0]), "+r"(d[1]), "+r"(d[2]), "+r"(d[3])
                 : "r"(a[0]), "r"(a[1]), "r"(a[2]), "r"(a[3]), "r"(b0), "r"(b1));
}
__device__ __forceinline__ float ex2f(float x) {
    float r; asm("ex2.approx.ftz.f32 %0, %1;" : "=f"(r) : "f"(x)); return r;
}
__device__ __forceinline__ float lg2f(float x) {
    float r; asm("lg2.approx.f32 %0, %1;" : "=f"(r) : "f"(x)); return r;
}

// ---------------------------------------------------------------------------
// Stage 0: per-row absmax int8 quantization.  grid (N_, 2), block 128.
// ---------------------------------------------------------------------------
__global__ void __launch_bounds__(128)
clip_quant(const float* __restrict__ A, const float* __restrict__ B)
{
    const float* src = blockIdx.y ? B : A;
    int8_t* dst = blockIdx.y ? g_Bq : g_Aq;
    float* sc   = blockIdx.y ? g_sB : g_sA;
    const int row = blockIdx.x;
    const int t = threadIdx.x;

    float4 v = *(const float4*)(src + (size_t)row * DDIM + t * 4);
    float am = fmaxf(fmaxf(fabsf(v.x), fabsf(v.y)), fmaxf(fabsf(v.z), fabsf(v.w)));
    #pragma unroll
    for (int o = 16; o >= 1; o >>= 1)
        am = fmaxf(am, __shfl_xor_sync(0xffffffffu, am, o));
    __shared__ float s[4];
    if ((t & 31) == 0) s[t >> 5] = am;
    __syncthreads();
    am = fmaxf(fmaxf(s[0], s[1]), fmaxf(s[2], s[3]));
    am = fmaxf(am, 1e-30f);
    const float inv = 127.0f / am;
    char4 q;
    q.x = (char)__float2int_rn(v.x * inv);
    q.y = (char)__float2int_rn(v.y * inv);
    q.z = (char)__float2int_rn(v.z * inv);
    q.w = (char)__float2int_rn(v.w * inv);
    *(char4*)(dst + (size_t)row * DDIM + t * 4) = q;
    if (t == 0) sc[row] = am * (1.0f / 127.0f);
}

// ---------------------------------------------------------------------------
// Stage 1: int8 mma.sync GEMM (128x128 tile, 2 CTAs/SM) + fused log2-LSE
// ---------------------------------------------------------------------------
__device__ __forceinline__ void load_stage(const int8_t* __restrict__ Ag,
                                           const int8_t* __restrict__ Bg,
                                           int it, int stage, uint32_t sb, int tid)
{
    const uint32_t baseA = sb + stage * STAGE_BYTES;
    const uint32_t baseB = baseA + A_BYTES;
    const int kb = it * BK;
    #pragma unroll
    for (int j = 0; j < 2; j++) {               // A: 128 rows x 4 chunks(16B)
        int idx = tid + j * 256;
        int row = idx >> 2, c = idx & 3;
        cp16(baseA + row * RSTRB + c * 16,
             Ag + (size_t)row * DDIM + kb + c * 16);
    }
    #pragma unroll
    for (int j = 0; j < 2; j++) {               // B: 128 rows x 4 chunks
        int idx = tid + j * 256;
        int row = idx >> 2, c = idx & 3;
        cp16(baseB + row * RSTRB + c * 16,
             Bg + (size_t)row * DDIM + kb + c * 16);
    }
    asm volatile("cp.async.commit_group;" ::: "memory");
}

__global__ void __launch_bounds__(256, 2)
clip_gemm_lse(const float* __restrict__ scale_p)
{
    extern __shared__ char smem[];
    const uint32_t sb = smem_u32(smem);
    const int tid  = threadIdx.x;
    const int wid  = tid >> 5;
    const int lane = tid & 31;
    const int gr   = lane >> 2;     // 0..7
    const int tc   = lane & 3;      // 0..3
    const int wm   = wid >> 2;      // 0..1 : 64-row block
    const int wn   = wid & 3;       // 0..3 : 32-col block

    const int8_t* Ag = g_Aq + (size_t)blockIdx.y * BM * DDIM;
    const int8_t* Bg = g_Bq + (size_t)blockIdx.x * BN * DDIM;

    int acc[4][4][4];
    #pragma unroll
    for (int mi = 0; mi < 4; mi++)
        #pragma unroll
        for (int ni = 0; ni < 4; ni++)
            #pragma unroll
            for (int c = 0; c < 4; c++) acc[mi][ni][c] = 0;

    load_stage(Ag, Bg, 0, 0, sb, tid);
    load_stage(Ag, Bg, 1, 1, sb, tid);
    load_stage(Ag, Bg, 2, 2, sb, tid);

    const int lrow = lane & 15;
    const int lk   = (lane >> 4) * 16;

    for (int it = 0; it < NIT; it++) {
        const int stage = it & 3;
        if (it < NIT - 3) asm volatile("cp.async.wait_group 2;" ::: "memory");
        else              asm volatile("cp.async.wait_group 0;" ::: "memory");
        __syncthreads();

        if (it + 3 < NIT) load_stage(Ag, Bg, it + 3, (it + 3) & 3, sb, tid);

        const uint32_t tA = sb + stage * STAGE_BYTES;
        const uint32_t tB = tA + A_BYTES;

        #pragma unroll
        for (int ks = 0; ks < 2; ks++) {        // two k32 steps per 64B chunk
            uint32_t af[4][4], bf[2][4];
            #pragma unroll
            for (int mi = 0; mi < 4; mi++) {
                int r = wm * 64 + mi * 16 + lrow;
                ldm_x4(af[mi], tA + r * RSTRB + ks * 32 + lk);
            }
            #pragma unroll
            for (int nj = 0; nj < 2; nj++) {
                int r = wn * 32 + nj * 16 + lrow;
                ldm_x4(bf[nj], tB + r * RSTRB + ks * 32 + lk);
            }
            #pragma unroll
            for (int mi = 0; mi < 4; mi++)
                #pragma unroll
                for (int ni = 0; ni < 4; ni++) {
                    const int nj = ni >> 1, odd = ni & 1;
                    mma_s8(acc[mi][ni], af[mi], bf[nj][odd], bf[nj][odd + 2]);
                }
        }
        __syncthreads();
    }

    // ---- dequantize in place: logits in log2 units ----
    const float w = __ldg(scale_p) * LOG2E;
    float sRow[8], sCol[8];
    #pragma unroll
    for (int mi = 0; mi < 4; mi++)
        #pragma unroll
        for (int h = 0; h < 2; h++)
            sRow[mi * 2 + h] = g_sA[blockIdx.y * BM + wm * 64 + mi * 16 + h * 8 + gr] * w;
    #pragma unroll
    for (int ni = 0; ni < 4; ni++)
        #pragma unroll
        for (int b = 0; b < 2; b++)
            sCol[ni * 2 + b] = g_sB[blockIdx.x * BN + wn * 32 + ni * 8 + tc * 2 + b];

    float* fa = reinterpret_cast<float*>(&acc[0][0][0]);
    #pragma unroll
    for (int mi = 0; mi < 4; mi++)
        #pragma unroll
        for (int ni = 0; ni < 4; ni++)
            #pragma unroll
            for (int c = 0; c < 4; c++) {
                int iv = acc[mi][ni][c];
                fa[(mi * 4 + ni) * 4 + c] =
                    (float)iv * sRow[mi * 2 + (c >> 1)] * sCol[ni * 2 + (c & 1)];
            }
    #define FACC(mi, ni, c) fa[((mi) * 4 + (ni)) * 4 + (c)]

    float* s_row  = (float*)smem;        // [4][128]
    float* s_col  = s_row + 512;         // [2][128]
    float* s_rowM = s_col + 256;         // [128]
    float* s_colM = s_rowM + 128;        // [128]
    float* s_rsum = s_colM + 128;        // [4][128]
    float* s_csum = s_rsum + 512;        // [2][128]

    // pass 1: maxes
    #pragma unroll
    for (int mi = 0; mi < 4; mi++)
        #pragma unroll
        for (int h = 0; h < 2; h++) {
            float m = -3.0e38f;
            #pragma unroll
            for (int ni = 0; ni < 4; ni++) {
                m = fmaxf(m, FACC(mi, ni, h * 2));
                m = fmaxf(m, FACC(mi, ni, h * 2 + 1));
            }
            m = fmaxf(m, __shfl_xor_sync(0xffffffffu, m, 1));
            m = fmaxf(m, __shfl_xor_sync(0xffffffffu, m, 2));
            if (tc == 0)
                s_row[wn * 128 + wm * 64 + mi * 16 + h * 8 + gr] = m;
        }
    #pragma unroll
    for (int ni = 0; ni < 4; ni++)
        #pragma unroll
        for (int b = 0; b < 2; b++) {
            float m = -3.0e38f;
            #pragma unroll
            for (int mi = 0; mi < 4; mi++) {
                m = fmaxf(m, FACC(mi, ni, b));
                m = fmaxf(m, FACC(mi, ni, 2 + b));
            }
            m = fmaxf(m, __shfl_xor_sync(0xffffffffu, m, 4));
            m = fmaxf(m, __shfl_xor_sync(0xffffffffu, m, 8));
            m = fmaxf(m, __shfl_xor_sync(0xffffffffu, m, 16));
            if (gr == 0)
                s_col[wm * 128 + wn * 32 + ni * 8 + tc * 2 + b] = m;
        }
    __syncthreads();
    if (tid < 128) {
        s_rowM[tid] = fmaxf(fmaxf(s_row[tid], s_row[128 + tid]),
                            fmaxf(s_row[256 + tid], s_row[384 + tid]));
    } else {
        int c = tid - 128;
        s_colM[c] = fmaxf(s_col[c], s_col[128 + c]);
    }
    __syncthreads();

    // pass 2: 2^(v-m) sums
    float rM[8], cM[8];
    #pragma unroll
    for (int mi = 0; mi < 4; mi++)
        #pragma unroll
        for (int h = 0; h < 2; h++)
            rM[mi * 2 + h] = s_rowM[wm * 64 + mi * 16 + h * 8 + gr];
    #pragma unroll
    for (int ni = 0; ni < 4; ni++)
        #pragma unroll
        for (int b = 0; b < 2; b++)
            cM[ni * 2 + b] = s_colM[wn * 32 + ni * 8 + tc * 2 + b];

    float csum[8];
    #pragma unroll
    for (int k = 0; k < 8; k++) csum[k] = 0.0f;

    #pragma unroll
    for (int mi = 0; mi < 4; mi++)
        #pragma unroll
        for (int h = 0; h < 2; h++) {
            float rs = 0.0f;
            const float rm = rM[mi * 2 + h];
            #pragma unroll
            for (int ni = 0; ni < 4; ni++)
                #pragma unroll
                for (int b = 0; b < 2; b++) {
                    float v = FACC(mi, ni, h * 2 + b);
                    rs += ex2f(v - rm);
                    csum[ni * 2 + b] += ex2f(v - cM[ni * 2 + b]);
                }
            rs += __shfl_xor_sync(0xffffffffu, rs, 1);
            rs += __shfl_xor_sync(0xffffffffu, rs, 2);
            if (tc == 0)
                s_rsum[wn * 128 + wm * 64 + mi * 16 + h * 8 + gr] = rs;
        }
    #pragma unroll
    for (int ni = 0; ni < 4; ni++)
        #pragma unroll
        for (int b = 0; b < 2; b++) {
            float cs = csum[ni * 2 + b];
            cs += __shfl_xor_sync(0xffffffffu, cs, 4);
            cs += __shfl_xor_sync(0xffffffffu, cs, 8);
            cs += __shfl_xor_sync(0xffffffffu, cs, 16);
            if (gr == 0)
                s_csum[wm * 128 + wn * 32 + ni * 8 + tc * 2 + b] = cs;
        }
    __syncthreads();

    if (tid < 128) {
        float rsum = s_rsum[tid] + s_rsum[128 + tid] + s_rsum[256 + tid] + s_rsum[384 + tid];
        g_rowPart[((size_t)blockIdx.y * BM + tid) * GT + blockIdx.x] =
            make_float2(s_rowM[tid], rsum);
    } else {
        int c = tid - 128;
        float cs = s_csum[c] + s_csum[128 + c];
        g_colPart[((size_t)blockIdx.x * BN + c) * GT + blockIdx.y] =
            make_float2(s_colM[c], cs);
    }
}

// ---------------------------------------------------------------------------
// Stage 2: combine 128 log2-domain partials per row/col, fp32 diag
// ---------------------------------------------------------------------------
__global__ void __launch_bounds__(128)
clip_finalize(const float* __restrict__ A, const float* __restrict__ B,
              const float* __restrict__ scale_p)
{
    __shared__ float red[128];
    const int r = blockIdx.x;
    const int t = threadIdx.x;

    float2 p = g_rowPart[(size_t)r * GT + t];
    red[t] = p.x;  __syncthreads();
    #pragma unroll
    for (int s = 64; s > 0; s >>= 1) { if (t < s) red[t] = fmaxf(red[t], red[t + s]); __syncthreads(); }
    const float Mr = red[0];  __syncthreads();
    red[t] = p.y * ex2f(p.x - Mr);  __syncthreads();
    #pragma unroll
    for (int s = 64; s > 0; s >>= 1) { if (t < s) red[t] += red[t + s]; __syncthreads(); }
    const float lse_r = LN2 * (Mr + lg2f(red[0]));  __syncthreads();

    float2 q = g_colPart[(size_t)r * GT + t];
    red[t] = q.x;  __syncthreads();
    #pragma unroll
    for (int s = 64; s > 0; s >>= 1) { if (t < s) red[t] = fmaxf(red[t], red[t + s]); __syncthreads(); }
    const float Mc = red[0];  __syncthreads();
    red[t] = q.y * ex2f(q.x - Mc);  __syncthreads();
    #pragma unroll
    for (int s = 64; s > 0; s >>= 1) { if (t < s) red[t] += red[t + s]; __syncthreads(); }
    const float lse_c = LN2 * (Mc + lg2f(red[0]));  __syncthreads();

    float d = 0.0f;
    #pragma unroll
    for (int k = t; k < DDIM; k += 128)
        d = fmaf(A[(size_t)r * DDIM + k], B[(size_t)r * DDIM + k], d);
    red[t] = d;  __syncthreads();
    #pragma unroll
    for (int s = 64; s > 0; s >>= 1) { if (t < s) red[t] += red[t + s]; __syncthreads(); }
    if (t == 0) {
        const float diag = (*scale_p) * red[0];
        g_contrib[r] = (lse_r - diag) + (lse_c - diag);
    }
}

__global__ void __launch_bounds__(256)
clip_reduce_final(float* __restrict__ out)
{
    __shared__ float red[256];
    const int t = threadIdx.x;
    float s = 0.0f;
    for (int r = t; r < N_; r += 256) s += g_contrib[r];
    red[t] = s;  __syncthreads();
    #pragma unroll
    for (int k = 128; k > 0; k >>= 1) { if (t < k) red[t] += red[t + k]; __syncthreads(); }
    if (t == 0) out[0] = red[0] * (0.5f / (float)N_);
}

// ---------------------------------------------------------------------------
extern "C" void kernel_launch(void* const* d_in, const int* in_sizes, int n_in,
                              void* d_out, int out_size)
{
    const float* img   = (const float*)d_in[0];
    const float* txt   = (const float*)d_in[1];
    const float* scale = (const float*)d_in[2];
    float* out = (float*)d_out;

    cudaFuncSetAttribute(clip_gemm_lse, cudaFuncAttributeMaxDynamicSharedMemorySize, SMEM_TOTAL);

    clip_quant<<<dim3(N_, 2), 128>>>(img, txt);
    clip_gemm_lse<<<dim3(GT, GT), 256, SMEM_TOTAL>>>(scale);
    clip_finalize<<<N_, 128>>>(img, txt, scale);
    clip_reduce_final<<<1, 256>>>(out);
}

// round 9
// speedup vs baseline: 9.4850x; 1.0658x over previous
#include <cuda_runtime.h>
#include <cuda_bf16.h>
#include <cstdint>

#define N_    16384
#define DDIM  512
#define BM    128
#define BN    128
#define BK    128              // int8 elems per k-chunk (128 B)
#define NIT   (DDIM / BK)      // 4
#define GT    (N_ / 128)       // 128 tiles per dim

#define RSTRB 144              // padded row stride bytes (128 data + 16 pad)
#define A_BYTES (BM * RSTRB)         // 18432
#define STAGE_BYTES (2 * A_BYTES)    // 36864
#define NSTAGE 3
#define SMEM_TOTAL (NSTAGE * STAGE_BYTES) // 110592

#define LOG2E 1.44269504088896f
#define LN2   0.69314718055995f

// ---------------- device scratch ----------------
__device__ __align__(16) int8_t g_Aq[(size_t)N_ * DDIM];   // 8 MB
__device__ __align__(16) int8_t g_Bq[(size_t)N_ * DDIM];   // 8 MB
__device__ float  g_sA[N_];
__device__ float  g_sB[N_];
__device__ float  g_diag[N_];                    // fp32 dot(A_r, B_r)
__device__ float2 g_rowPart[(size_t)N_ * GT];    // 16 MB (log2-domain)
__device__ float2 g_colPart[(size_t)N_ * GT];    // 16 MB
__device__ float  g_contrib[N_];

// ---------------- helpers ----------------
__device__ __forceinline__ uint32_t smem_u32(const void* p) {
    uint32_t a;
    asm("{ .reg .u64 t; cvta.to.shared.u64 t, %1; cvt.u32.u64 %0, t; }" : "=r"(a) : "l"(p));
    return a;
}
__device__ __forceinline__ void cp16(uint32_t sa, const void* g) {
    asm volatile("cp.async.cg.shared.global [%0], [%1], 16;" :: "r"(sa), "l"(g) : "memory");
}
__device__ __forceinline__ void ldm_x4(uint32_t* d, uint32_t addr) {
    asm volatile("ldmatrix.sync.aligned.m8n8.x4.shared.b16 {%0,%1,%2,%3}, [%4];"
                 : "=r"(d[0]), "=r"(d[1]), "=r"(d[2]), "=r"(d[3]) : "r"(addr));
}
__device__ __forceinline__ void mma_s8(int* d, const uint32_t* a, uint32_t b0, uint32_t b1) {
    asm volatile("mma.sync.aligned.m16n8k32.row.col.s32.s8.s8.s32 "
                 "{%0,%1,%2,%3}, {%4,%5,%6,%7}, {%8,%9}, {%0,%1,%2,%3};"
                 : "+r"(d[0]), "+r"(d[1]), "+r"(d[2]), "+r"(d[3])
                 : "r"(a[0]), "r"(a[1]), "r"(a[2]), "r"(a[3]), "r"(b0), "r"(b1));
}
__device__ __forceinline__ float ex2f(float x) {
    float r; asm("ex2.approx.ftz.f32 %0, %1;" : "=f"(r) : "f"(x)); return r;
}
__device__ __forceinline__ float lg2f(float x) {
    float r; asm("lg2.approx.f32 %0, %1;" : "=f"(r) : "f"(x)); return r;
}

// ---------------------------------------------------------------------------
// Stage 0: per-row absmax int8 quantization of BOTH matrices + fp32 diag.
// grid N_, block 128. Each block: row r of A and row r of B.
// ---------------------------------------------------------------------------
__global__ void __launch_bounds__(128)
clip_quant(const float* __restrict__ A, const float* __restrict__ B)
{
    const int row = blockIdx.x;
    const int t = threadIdx.x;
    __shared__ float sa[4], sbm[4], sd[4];

    float4 va = *(const float4*)(A + (size_t)row * DDIM + t * 4);
    float4 vb = *(const float4*)(B + (size_t)row * DDIM + t * 4);

    float ama = fmaxf(fmaxf(fabsf(va.x), fabsf(va.y)), fmaxf(fabsf(va.z), fabsf(va.w)));
    float amb = fmaxf(fmaxf(fabsf(vb.x), fabsf(vb.y)), fmaxf(fabsf(vb.z), fabsf(vb.w)));
    float d = va.x * vb.x + va.y * vb.y + va.z * vb.z + va.w * vb.w;
    #pragma unroll
    for (int o = 16; o >= 1; o >>= 1) {
        ama = fmaxf(ama, __shfl_xor_sync(0xffffffffu, ama, o));
        amb = fmaxf(amb, __shfl_xor_sync(0xffffffffu, amb, o));
        d += __shfl_xor_sync(0xffffffffu, d, o);
    }
    if ((t & 31) == 0) { sa[t >> 5] = ama; sbm[t >> 5] = amb; sd[t >> 5] = d; }
    __syncthreads();
    ama = fmaxf(fmaxf(sa[0], sa[1]), fmaxf(sa[2], sa[3]));
    amb = fmaxf(fmaxf(sbm[0], sbm[1]), fmaxf(sbm[2], sbm[3]));
    ama = fmaxf(ama, 1e-30f);
    amb = fmaxf(amb, 1e-30f);

    const float ia = 127.0f / ama;
    const float ib = 127.0f / amb;
    char4 qa, qb;
    qa.x = (char)__float2int_rn(va.x * ia); qa.y = (char)__float2int_rn(va.y * ia);
    qa.z = (char)__float2int_rn(va.z * ia); qa.w = (char)__float2int_rn(va.w * ia);
    qb.x = (char)__float2int_rn(vb.x * ib); qb.y = (char)__float2int_rn(vb.y * ib);
    qb.z = (char)__float2int_rn(vb.z * ib); qb.w = (char)__float2int_rn(vb.w * ib);
    *(char4*)(g_Aq + (size_t)row * DDIM + t * 4) = qa;
    *(char4*)(g_Bq + (size_t)row * DDIM + t * 4) = qb;
    if (t == 0) {
        g_sA[row] = ama * (1.0f / 127.0f);
        g_sB[row] = amb * (1.0f / 127.0f);
        g_diag[row] = sd[0] + sd[1] + sd[2] + sd[3];
    }
}

// ---------------------------------------------------------------------------
// Stage 1: int8 mma.sync GEMM (128x128 tile, 2 CTAs/SM) + fused log2-LSE
// ---------------------------------------------------------------------------
__device__ __forceinline__ void load_stage(const int8_t* __restrict__ Ag,
                                           const int8_t* __restrict__ Bg,
                                           int it, int stage, uint32_t sb, int tid)
{
    const uint32_t baseA = sb + stage * STAGE_BYTES;
    const uint32_t baseB = baseA + A_BYTES;
    const int kb = it * BK;
    #pragma unroll
    for (int j = 0; j < 4; j++) {               // A: 128 rows x 8 chunks(16B)
        int idx = tid + j * 256;
        int row = idx >> 3, c = idx & 7;
        cp16(baseA + row * RSTRB + c * 16,
             Ag + (size_t)row * DDIM + kb + c * 16);
    }
    #pragma unroll
    for (int j = 0; j < 4; j++) {               // B: 128 rows x 8 chunks
        int idx = tid + j * 256;
        int row = idx >> 3, c = idx & 7;
        cp16(baseB + row * RSTRB + c * 16,
             Bg + (size_t)row * DDIM + kb + c * 16);
    }
    asm volatile("cp.async.commit_group;" ::: "memory");
}

__global__ void __launch_bounds__(256, 2)
clip_gemm_lse(const float* __restrict__ scale_p)
{
    extern __shared__ char smem[];
    const uint32_t sb = smem_u32(smem);
    const int tid  = threadIdx.x;
    const int wid  = tid >> 5;
    const int lane = tid & 31;
    const int gr   = lane >> 2;     // 0..7
    const int tc   = lane & 3;      // 0..3
    const int wm   = wid >> 2;      // 0..1 : 64-row block
    const int wn   = wid & 3;       // 0..3 : 32-col block

    const int8_t* Ag = g_Aq + (size_t)blockIdx.y * BM * DDIM;
    const int8_t* Bg = g_Bq + (size_t)blockIdx.x * BN * DDIM;

    int acc[4][4][4];
    #pragma unroll
    for (int mi = 0; mi < 4; mi++)
        #pragma unroll
        for (int ni = 0; ni < 4; ni++)
            #pragma unroll
            for (int c = 0; c < 4; c++) acc[mi][ni][c] = 0;

    load_stage(Ag, Bg, 0, 0, sb, tid);
    load_stage(Ag, Bg, 1, 1, sb, tid);

    const int lrow = lane & 15;
    const int lk   = (lane >> 4) * 16;

    for (int it = 0; it < NIT; it++) {
        const int stage = it % NSTAGE;
        if (it < NIT - 2) asm volatile("cp.async.wait_group 1;" ::: "memory");
        else              asm volatile("cp.async.wait_group 0;" ::: "memory");
        __syncthreads();

        if (it + 2 < NIT) load_stage(Ag, Bg, it + 2, (it + 2) % NSTAGE, sb, tid);

        const uint32_t tA = sb + stage * STAGE_BYTES;
        const uint32_t tB = tA + A_BYTES;

        #pragma unroll
        for (int ks = 0; ks < 4; ks++) {        // four k32 steps per 128B chunk
            uint32_t af[4][4], bf[2][4];
            #pragma unroll
            for (int mi = 0; mi < 4; mi++) {
                int r = wm * 64 + mi * 16 + lrow;
                ldm_x4(af[mi], tA + r * RSTRB + ks * 32 + lk);
            }
            #pragma unroll
            for (int nj = 0; nj < 2; nj++) {
                int r = wn * 32 + nj * 16 + lrow;
                ldm_x4(bf[nj], tB + r * RSTRB + ks * 32 + lk);
            }
            #pragma unroll
            for (int mi = 0; mi < 4; mi++)
                #pragma unroll
                for (int ni = 0; ni < 4; ni++) {
                    const int nj = ni >> 1, odd = ni & 1;
                    mma_s8(acc[mi][ni], af[mi], bf[nj][odd], bf[nj][odd + 2]);
                }
        }
        __syncthreads();
    }

    // ---- dequantize in place: logits in log2 units ----
    const float w = __ldg(scale_p) * LOG2E;
    float sRow[8], sCol[8];
    #pragma unroll
    for (int mi = 0; mi < 4; mi++)
        #pragma unroll
        for (int h = 0; h < 2; h++)
            sRow[mi * 2 + h] = g_sA[blockIdx.y * BM + wm * 64 + mi * 16 + h * 8 + gr] * w;
    #pragma unroll
    for (int ni = 0; ni < 4; ni++)
        #pragma unroll
        for (int b = 0; b < 2; b++)
            sCol[ni * 2 + b] = g_sB[blockIdx.x * BN + wn * 32 + ni * 8 + tc * 2 + b];

    float* fa = reinterpret_cast<float*>(&acc[0][0][0]);
    #pragma unroll
    for (int mi = 0; mi < 4; mi++)
        #pragma unroll
        for (int ni = 0; ni < 4; ni++)
            #pragma unroll
            for (int c = 0; c < 4; c++) {
                int iv = acc[mi][ni][c];
                fa[(mi * 4 + ni) * 4 + c] =
                    (float)iv * sRow[mi * 2 + (c >> 1)] * sCol[ni * 2 + (c & 1)];
            }
    #define FACC(mi, ni, c) fa[((mi) * 4 + (ni)) * 4 + (c)]

    // Epilogue smem overlay at stage-1 offset: last iteration consumed stage 0,
    // stages 1 and 2 are dead here (their data was consumed at it=1,2).
    float* ep     = (float*)(smem + STAGE_BYTES);
    float* s_row  = ep;                  // [4][128]
    float* s_col  = s_row + 512;         // [2][128]
    float* s_rowM = s_col + 256;         // [128]
    float* s_colM = s_rowM + 128;        // [128]
    float* s_rsum = s_colM + 128;        // [4][128]
    float* s_csum = s_rsum + 512;        // [2][128]

    // pass 1: maxes
    #pragma unroll
    for (int mi = 0; mi < 4; mi++)
        #pragma unroll
        for (int h = 0; h < 2; h++) {
            float m = -3.0e38f;
            #pragma unroll
            for (int ni = 0; ni < 4; ni++) {
                m = fmaxf(m, FACC(mi, ni, h * 2));
                m = fmaxf(m, FACC(mi, ni, h * 2 + 1));
            }
            m = fmaxf(m, __shfl_xor_sync(0xffffffffu, m, 1));
            m = fmaxf(m, __shfl_xor_sync(0xffffffffu, m, 2));
            if (tc == 0)
                s_row[wn * 128 + wm * 64 + mi * 16 + h * 8 + gr] = m;
        }
    #pragma unroll
    for (int ni = 0; ni < 4; ni++)
        #pragma unroll
        for (int b = 0; b < 2; b++) {
            float m = -3.0e38f;
            #pragma unroll
            for (int mi = 0; mi < 4; mi++) {
                m = fmaxf(m, FACC(mi, ni, b));
                m = fmaxf(m, FACC(mi, ni, 2 + b));
            }
            m = fmaxf(m, __shfl_xor_sync(0xffffffffu, m, 4));
            m = fmaxf(m, __shfl_xor_sync(0xffffffffu, m, 8));
            m = fmaxf(m, __shfl_xor_sync(0xffffffffu, m, 16));
            if (gr == 0)
                s_col[wm * 128 + wn * 32 + ni * 8 + tc * 2 + b] = m;
        }
    __syncthreads();
    if (tid < 128) {
        s_rowM[tid] = fmaxf(fmaxf(s_row[tid], s_row[128 + tid]),
                            fmaxf(s_row[256 + tid], s_row[384 + tid]));
    } else {
        int c = tid - 128;
        s_colM[c] = fmaxf(s_col[c], s_col[128 + c]);
    }
    __syncthreads();

    // pass 2: 2^(v-m) sums
    float rM[8], cM[8];
    #pragma unroll
    for (int mi = 0; mi < 4; mi++)
        #pragma unroll
        for (int h = 0; h < 2; h++)
            rM[mi * 2 + h] = s_rowM[wm * 64 + mi * 16 + h * 8 + gr];
    #pragma unroll
    for (int ni = 0; ni < 4; ni++)
        #pragma unroll
        for (int b = 0; b < 2; b++)
            cM[ni * 2 + b] = s_colM[wn * 32 + ni * 8 + tc * 2 + b];

    float csum[8];
    #pragma unroll
    for (int k = 0; k < 8; k++) csum[k] = 0.0f;

    #pragma unroll
    for (int mi = 0; mi < 4; mi++)
        #pragma unroll
        for (int h = 0; h < 2; h++) {
            float rs = 0.0f;
            const float rm = rM[mi * 2 + h];
            #pragma unroll
            for (int ni = 0; ni < 4; ni++)
                #pragma unroll
                for (int b = 0; b < 2; b++) {
                    float v = FACC(mi, ni, h * 2 + b);
                    rs += ex2f(v - rm);
                    csum[ni * 2 + b] += ex2f(v - cM[ni * 2 + b]);
                }
            rs += __shfl_xor_sync(0xffffffffu, rs, 1);
            rs += __shfl_xor_sync(0xffffffffu, rs, 2);
            if (tc == 0)
                s_rsum[wn * 128 + wm * 64 + mi * 16 + h * 8 + gr] = rs;
        }
    #pragma unroll
    for (int ni = 0; ni < 4; ni++)
        #pragma unroll
        for (int b = 0; b < 2; b++) {
            float cs = csum[ni * 2 + b];
            cs += __shfl_xor_sync(0xffffffffu, cs, 4);
            cs += __shfl_xor_sync(0xffffffffu, cs, 8);
            cs += __shfl_xor_sync(0xffffffffu, cs, 16);
            if (gr == 0)
                s_csum[wm * 128 + wn * 32 + ni * 8 + tc * 2 + b] = cs;
        }
    __syncthreads();

    if (tid < 128) {
        float rsum = s_rsum[tid] + s_rsum[128 + tid] + s_rsum[256 + tid] + s_rsum[384 + tid];
        g_rowPart[((size_t)blockIdx.y * BM + tid) * GT + blockIdx.x] =
            make_float2(s_rowM[tid], rsum);
    } else {
        int c = tid - 128;
        float cs = s_csum[c] + s_csum[128 + c];
        g_colPart[((size_t)blockIdx.x * BN + c) * GT + blockIdx.y] =
            make_float2(s_colM[c], cs);
    }
}

// ---------------------------------------------------------------------------
// Stage 2: combine 128 log2-domain partials per row/col + precomputed diag
// ---------------------------------------------------------------------------
__global__ void __launch_bounds__(128)
clip_finalize(const float* __restrict__ scale_p)
{
    __shared__ float red[128];
    const int r = blockIdx.x;
    const int t = threadIdx.x;

    float2 p = g_rowPart[(size_t)r * GT + t];
    red[t] = p.x;  __syncthreads();
    #pragma unroll
    for (int s = 64; s > 0; s >>= 1) { if (t < s) red[t] = fmaxf(red[t], red[t + s]); __syncthreads(); }
    const float Mr = red[0];  __syncthreads();
    red[t] = p.y * ex2f(p.x - Mr);  __syncthreads();
    #pragma unroll
    for (int s = 64; s > 0; s >>= 1) { if (t < s) red[t] += red[t + s]; __syncthreads(); }
    const float lse_r = LN2 * (Mr + lg2f(red[0]));  __syncthreads();

    float2 q = g_colPart[(size_t)r * GT + t];
    red[t] = q.x;  __syncthreads();
    #pragma unroll
    for (int s = 64; s > 0; s >>= 1) { if (t < s) red[t] = fmaxf(red[t], red[t + s]); __syncthreads(); }
    const float Mc = red[0];  __syncthreads();
    red[t] = q.y * ex2f(q.x - Mc);  __syncthreads();
    #pragma unroll
    for (int s = 64; s > 0; s >>= 1) { if (t < s) red[t] += red[t + s]; __syncthreads(); }
    const float lse_c = LN2 * (Mc + lg2f(red[0]));

    if (t == 0) {
        const float diag = (*scale_p) * g_diag[r];
        g_contrib[r] = (lse_r - diag) + (lse_c - diag);
    }
}

__global__ void __launch_bounds__(256)
clip_reduce_final(float* __restrict__ out)
{
    __shared__ float red[256];
    const int t = threadIdx.x;
    float s = 0.0f;
    const float4* c4 = (const float4*)g_contrib;
    for (int r = t; r < N_ / 4; r += 256) {
        float4 v = c4[r];
        s += (v.x + v.y) + (v.z + v.w);
    }
    red[t] = s;  __syncthreads();
    #pragma unroll
    for (int k = 128; k > 0; k >>= 1) { if (t < k) red[t] += red[t + k]; __syncthreads(); }
    if (t == 0) out[0] = red[0] * (0.5f / (float)N_);
}

// ---------------------------------------------------------------------------
extern "C" void kernel_launch(void* const* d_in, const int* in_sizes, int n_in,
                              void* d_out, int out_size)
{
    const float* img   = (const float*)d_in[0];
    const float* txt   = (const float*)d_in[1];
    const float* scale = (const float*)d_in[2];
    float* out = (float*)d_out;

    cudaFuncSetAttribute(clip_gemm_lse, cudaFuncAttributeMaxDynamicSharedMemorySize, SMEM_TOTAL);

    clip_quant<<<N_, 128>>>(img, txt);
    clip_gemm_lse<<<dim3(GT, GT), 256, SMEM_TOTAL>>>(scale);
    clip_finalize<<<N_, 128>>>(scale);
    clip_reduce_final<<<1, 256>>>(out);
}

// round 11
// speedup vs baseline: 9.6916x; 1.0218x over previous
#include <cuda_runtime.h>
#include <cuda_bf16.h>
#include <cstdint>

#define N_    16384
#define DDIM  512
#define BM    128
#define BN    128
#define BK    128              // int8 elems per k-chunk (128 B)
#define NIT   (DDIM / BK)      // 4
#define GT    (N_ / 128)       // 128 tiles per dim

#define RSTRB 144              // padded row stride bytes (128 data + 16 pad)
#define A_BYTES (BM * RSTRB)         // 18432
#define STAGE_BYTES (2 * A_BYTES)    // 36864
#define NSTAGE 3
#define SMEM_TOTAL (NSTAGE * STAGE_BYTES) // 110592

#define LOG2E 1.44269504088896f
#define LN2   0.69314718055995f

// ---------------- device scratch ----------------
__device__ __align__(16) int8_t g_Aq[(size_t)N_ * DDIM];   // 8 MB
__device__ __align__(16) int8_t g_Bq[(size_t)N_ * DDIM];   // 8 MB
__device__ float  g_sA[N_];
__device__ float  g_sB[N_];
__device__ float  g_diag[N_];                    // fp32 dot(A_r, B_r)
__device__ float2 g_rowPart[(size_t)N_ * GT];    // 16 MB (log2-domain)
__device__ float2 g_colPart[(size_t)N_ * GT];    // 16 MB
__device__ float  g_contrib[N_];

// ---------------- helpers ----------------
__device__ __forceinline__ uint32_t smem_u32(const void* p) {
    uint32_t a;
    asm("{ .reg .u64 t; cvta.to.shared.u64 t, %1; cvt.u32.u64 %0, t; }" : "=r"(a) : "l"(p));
    return a;
}
__device__ __forceinline__ void cp16(uint32_t sa, const void* g) {
    asm volatile("cp.async.cg.shared.global [%0], [%1], 16;" :: "r"(sa), "l"(g) : "memory");
}
__device__ __forceinline__ void ldm_x4(uint32_t* d, uint32_t addr) {
    asm volatile("ldmatrix.sync.aligned.m8n8.x4.shared.b16 {%0,%1,%2,%3}, [%4];"
                 : "=r"(d[0]), "=r"(d[1]), "=r"(d[2]), "=r"(d[3]) : "r"(addr));
}
__device__ __forceinline__ void mma_s8(int* d, const uint32_t* a, uint32_t b0, uint32_t b1) {
    asm volatile("mma.sync.aligned.m16n8k32.row.col.s32.s8.s8.s32 "
                 "{%0,%1,%2,%3}, {%4,%5,%6,%7}, {%8,%9}, {%0,%1,%2,%3};"
                 : "+r"(d[0]), "+r"(d[1]), "+r"(d[2]), "+r"(d[3])
                 : "r"(a[0]), "r"(a[1]), "r"(a[2]), "r"(a[3]), "r"(b0), "r"(b1));
}
__device__ __forceinline__ float ex2f(float x) {
    float r; asm("ex2.approx.ftz.f32 %0, %1;" : "=f"(r) : "f"(x)); return r;
}
__device__ __forceinline__ float lg2f(float x) {
    float r; asm("lg2.approx.f32 %0, %1;" : "=f"(r) : "f"(x)); return r;
}

// ---------------------------------------------------------------------------
// Stage 0: per-row absmax int8 quantization of BOTH matrices + fp32 diag.
// ---------------------------------------------------------------------------
__global__ void __launch_bounds__(128)
clip_quant(const float* __restrict__ A, const float* __restrict__ B)
{
    const int row = blockIdx.x;
    const int t = threadIdx.x;
    __shared__ float sa[4], sbm[4], sd[4];

    float4 va = *(const float4*)(A + (size_t)row * DDIM + t * 4);
    float4 vb = *(const float4*)(B + (size_t)row * DDIM + t * 4);

    float ama = fmaxf(fmaxf(fabsf(va.x), fabsf(va.y)), fmaxf(fabsf(va.z), fabsf(va.w)));
    float amb = fmaxf(fmaxf(fabsf(vb.x), fabsf(vb.y)), fmaxf(fabsf(vb.z), fabsf(vb.w)));
    float d = va.x * vb.x + va.y * vb.y + va.z * vb.z + va.w * vb.w;
    #pragma unroll
    for (int o = 16; o >= 1; o >>= 1) {
        ama = fmaxf(ama, __shfl_xor_sync(0xffffffffu, ama, o));
        amb = fmaxf(amb, __shfl_xor_sync(0xffffffffu, amb, o));
        d += __shfl_xor_sync(0xffffffffu, d, o);
    }
    if ((t & 31) == 0) { sa[t >> 5] = ama; sbm[t >> 5] = amb; sd[t >> 5] = d; }
    __syncthreads();
    ama = fmaxf(fmaxf(sa[0], sa[1]), fmaxf(sa[2], sa[3]));
    amb = fmaxf(fmaxf(sbm[0], sbm[1]), fmaxf(sbm[2], sbm[3]));
    ama = fmaxf(ama, 1e-30f);
    amb = fmaxf(amb, 1e-30f);

    const float ia = 127.0f / ama;
    const float ib = 127.0f / amb;
    char4 qa, qb;
    qa.x = (char)__float2int_rn(va.x * ia); qa.y = (char)__float2int_rn(va.y * ia);
    qa.z = (char)__float2int_rn(va.z * ia); qa.w = (char)__float2int_rn(va.w * ia);
    qb.x = (char)__float2int_rn(vb.x * ib); qb.y = (char)__float2int_rn(vb.y * ib);
    qb.z = (char)__float2int_rn(vb.z * ib); qb.w = (char)__float2int_rn(vb.w * ib);
    *(char4*)(g_Aq + (size_t)row * DDIM + t * 4) = qa;
    *(char4*)(g_Bq + (size_t)row * DDIM + t * 4) = qb;
    if (t == 0) {
        g_sA[row] = ama * (1.0f / 127.0f);
        g_sB[row] = amb * (1.0f / 127.0f);
        g_diag[row] = sd[0] + sd[1] + sd[2] + sd[3];
    }
}

// ---------------------------------------------------------------------------
// Stage 1: int8 mma.sync GEMM (128x128 tile, 2 CTAs/SM) + fused log2-LSE
// ---------------------------------------------------------------------------
__device__ __forceinline__ void load_stage(const int8_t* __restrict__ Ag,
                                           const int8_t* __restrict__ Bg,
                                           int it, int stage, uint32_t sb, int tid)
{
    const uint32_t baseA = sb + stage * STAGE_BYTES;
    const uint32_t baseB = baseA + A_BYTES;
    const int kb = it * BK;
    #pragma unroll
    for (int j = 0; j < 4; j++) {               // A: 128 rows x 8 chunks(16B)
        int idx = tid + j * 256;
        int row = idx >> 3, c = idx & 7;
        cp16(baseA + row * RSTRB + c * 16,
             Ag + (size_t)row * DDIM + kb + c * 16);
    }
    #pragma unroll
    for (int j = 0; j < 4; j++) {               // B: 128 rows x 8 chunks
        int idx = tid + j * 256;
        int row = idx >> 3, c = idx & 7;
        cp16(baseB + row * RSTRB + c * 16,
             Bg + (size_t)row * DDIM + kb + c * 16);
    }
    asm volatile("cp.async.commit_group;" ::: "memory");
}

__global__ void __launch_bounds__(256, 2)
clip_gemm_lse(const float* __restrict__ scale_p)
{
    extern __shared__ char smem[];
    const uint32_t sb = smem_u32(smem);
    const int tid  = threadIdx.x;
    const int wid  = tid >> 5;
    const int lane = tid & 31;
    const int gr   = lane >> 2;     // 0..7
    const int tc   = lane & 3;      // 0..3
    const int wm   = wid >> 2;      // 0..1 : 64-row block
    const int wn   = wid & 3;       // 0..3 : 32-col block

    const int8_t* Ag = g_Aq + (size_t)blockIdx.y * BM * DDIM;
    const int8_t* Bg = g_Bq + (size_t)blockIdx.x * BN * DDIM;

    int acc[4][4][4];
    #pragma unroll
    for (int mi = 0; mi < 4; mi++)
        #pragma unroll
        for (int ni = 0; ni < 4; ni++)
            #pragma unroll
            for (int c = 0; c < 4; c++) acc[mi][ni][c] = 0;

    load_stage(Ag, Bg, 0, 0, sb, tid);
    load_stage(Ag, Bg, 1, 1, sb, tid);

    const int lrow = lane & 15;
    const int lk   = (lane >> 4) * 16;

    for (int it = 0; it < NIT; it++) {
        const int stage = it % NSTAGE;
        if (it < NIT - 2) asm volatile("cp.async.wait_group 1;" ::: "memory");
        else              asm volatile("cp.async.wait_group 0;" ::: "memory");
        __syncthreads();

        if (it + 2 < NIT) load_stage(Ag, Bg, it + 2, (it + 2) % NSTAGE, sb, tid);

        const uint32_t tA = sb + stage * STAGE_BYTES;
        const uint32_t tB = tA + A_BYTES;

        #pragma unroll
        for (int ks = 0; ks < 4; ks++) {        // four k32 steps per 128B chunk
            uint32_t af[4][4], bf[2][4];
            #pragma unroll
            for (int mi = 0; mi < 4; mi++) {
                int r = wm * 64 + mi * 16 + lrow;
                ldm_x4(af[mi], tA + r * RSTRB + ks * 32 + lk);
            }
            #pragma unroll
            for (int nj = 0; nj < 2; nj++) {
                int r = wn * 32 + nj * 16 + lrow;
                ldm_x4(bf[nj], tB + r * RSTRB + ks * 32 + lk);
            }
            #pragma unroll
            for (int mi = 0; mi < 4; mi++)
                #pragma unroll
                for (int ni = 0; ni < 4; ni++) {
                    const int nj = ni >> 1, odd = ni & 1;
                    mma_s8(acc[mi][ni], af[mi], bf[nj][odd], bf[nj][odd + 2]);
                }
        }
        __syncthreads();
    }

    // ---- dequantize in place: logits in log2 units ----
    const float w = __ldg(scale_p) * LOG2E;
    float sRow[8], sCol[8];
    #pragma unroll
    for (int mi = 0; mi < 4; mi++)
        #pragma unroll
        for (int h = 0; h < 2; h++)
            sRow[mi * 2 + h] = g_sA[blockIdx.y * BM + wm * 64 + mi * 16 + h * 8 + gr] * w;
    #pragma unroll
    for (int ni = 0; ni < 4; ni++)
        #pragma unroll
        for (int b = 0; b < 2; b++)
            sCol[ni * 2 + b] = g_sB[blockIdx.x * BN + wn * 32 + ni * 8 + tc * 2 + b];

    float* fa = reinterpret_cast<float*>(&acc[0][0][0]);
    #pragma unroll
    for (int mi = 0; mi < 4; mi++)
        #pragma unroll
        for (int ni = 0; ni < 4; ni++)
            #pragma unroll
            for (int c = 0; c < 4; c++) {
                int iv = acc[mi][ni][c];
                fa[(mi * 4 + ni) * 4 + c] =
                    (float)iv * sRow[mi * 2 + (c >> 1)] * sCol[ni * 2 + (c & 1)];
            }
    #define FACC(mi, ni, c) fa[((mi) * 4 + (ni)) * 4 + (c)]

    // Epilogue smem overlay at stage-1 offset (stages 1,2 dead after mainloop).
    float* ep     = (float*)(smem + STAGE_BYTES);
    float* s_row  = ep;                  // [4][128]
    float* s_col  = s_row + 512;         // [2][128]
    float* s_rowM = s_col + 256;         // [128]
    float* s_colM = s_rowM + 128;        // [128]
    float* s_rsum = s_colM + 128;        // [4][128]
    float* s_csum = s_rsum + 512;        // [2][128]

    // pass 1: maxes
    #pragma unroll
    for (int mi = 0; mi < 4; mi++)
        #pragma unroll
        for (int h = 0; h < 2; h++) {
            float m = -3.0e38f;
            #pragma unroll
            for (int ni = 0; ni < 4; ni++) {
                m = fmaxf(m, FACC(mi, ni, h * 2));
                m = fmaxf(m, FACC(mi, ni, h * 2 + 1));
            }
            m = fmaxf(m, __shfl_xor_sync(0xffffffffu, m, 1));
            m = fmaxf(m, __shfl_xor_sync(0xffffffffu, m, 2));
            if (tc == 0)
                s_row[wn * 128 + wm * 64 + mi * 16 + h * 8 + gr] = m;
        }
    #pragma unroll
    for (int ni = 0; ni < 4; ni++)
        #pragma unroll
        for (int b = 0; b < 2; b++) {
            float m = -3.0e38f;
            #pragma unroll
            for (int mi = 0; mi < 4; mi++) {
                m = fmaxf(m, FACC(mi, ni, b));
                m = fmaxf(m, FACC(mi, ni, 2 + b));
            }
            m = fmaxf(m, __shfl_xor_sync(0xffffffffu, m, 4));
            m = fmaxf(m, __shfl_xor_sync(0xffffffffu, m, 8));
            m = fmaxf(m, __shfl_xor_sync(0xffffffffu, m, 16));
            if (gr == 0)
                s_col[wm * 128 + wn * 32 + ni * 8 + tc * 2 + b] = m;
        }
    __syncthreads();
    if (tid < 128) {
        s_rowM[tid] = fmaxf(fmaxf(s_row[tid], s_row[128 + tid]),
                            fmaxf(s_row[256 + tid], s_row[384 + tid]));
    } else {
        int c = tid - 128;
        s_colM[c] = fmaxf(s_col[c], s_col[128 + c]);
    }
    __syncthreads();

    // pass 2: 2^(v-m) sums
    float rM[8], cM[8];
    #pragma unroll
    for (int mi = 0; mi < 4; mi++)
        #pragma unroll
        for (int h = 0; h < 2; h++)
            rM[mi * 2 + h] = s_rowM[wm * 64 + mi * 16 + h * 8 + gr];
    #pragma unroll
    for (int ni = 0; ni < 4; ni++)
        #pragma unroll
        for (int b = 0; b < 2; b++)
            cM[ni * 2 + b] = s_colM[wn * 32 + ni * 8 + tc * 2 + b];

    float csum[8];
    #pragma unroll
    for (int k = 0; k < 8; k++) csum[k] = 0.0f;

    #pragma unroll
    for (int mi = 0; mi < 4; mi++)
        #pragma unroll
        for (int h = 0; h < 2; h++) {
            float rs = 0.0f;
            const float rm = rM[mi * 2 + h];
            #pragma unroll
            for (int ni = 0; ni < 4; ni++)
                #pragma unroll
                for (int b = 0; b < 2; b++) {
                    float v = FACC(mi, ni, h * 2 + b);
                    rs += ex2f(v - rm);
                    csum[ni * 2 + b] += ex2f(v - cM[ni * 2 + b]);
                }
            rs += __shfl_xor_sync(0xffffffffu, rs, 1);
            rs += __shfl_xor_sync(0xffffffffu, rs, 2);
            if (tc == 0)
                s_rsum[wn * 128 + wm * 64 + mi * 16 + h * 8 + gr] = rs;
        }
    #pragma unroll
    for (int ni = 0; ni < 4; ni++)
        #pragma unroll
        for (int b = 0; b < 2; b++) {
            float cs = csum[ni * 2 + b];
            cs += __shfl_xor_sync(0xffffffffu, cs, 4);
            cs += __shfl_xor_sync(0xffffffffu, cs, 8);
            cs += __shfl_xor_sync(0xffffffffu, cs, 16);
            if (gr == 0)
                s_csum[wm * 128 + wn * 32 + ni * 8 + tc * 2 + b] = cs;
        }
    __syncthreads();

    if (tid < 128) {
        float rsum = s_rsum[tid] + s_rsum[128 + tid] + s_rsum[256 + tid] + s_rsum[384 + tid];
        g_rowPart[((size_t)blockIdx.y * BM + tid) * GT + blockIdx.x] =
            make_float2(s_rowM[tid], rsum);
    } else {
        int c = tid - 128;
        float cs = s_csum[c] + s_csum[128 + c];
        g_colPart[((size_t)blockIdx.x * BN + c) * GT + blockIdx.y] =
            make_float2(s_colM[c], cs);
    }
}

// ---------------------------------------------------------------------------
// Stage 2: row and col LSE computed concurrently by thread halves; shuffles
// replace smem trees (4 syncs vs ~28).
// ---------------------------------------------------------------------------
__global__ void __launch_bounds__(256)
clip_finalize(const float* __restrict__ scale_p)
{
    __shared__ float s_m[8], s_s[8], s_lse[2];
    const int r = blockIdx.x;
    const int t = threadIdx.x;
    const int half = t >> 7;          // 0 = row, 1 = col
    const int j = t & 127;
    const int wslot = t >> 5;         // 0..7 (4 warps per half)

    float2 p = half ? g_colPart[(size_t)r * GT + j]
                    : g_rowPart[(size_t)r * GT + j];

    // warp-level max
    float m = p.x;
    #pragma unroll
    for (int o = 16; o >= 1; o >>= 1)
        m = fmaxf(m, __shfl_xor_sync(0xffffffffu, m, o));
    if ((t & 31) == 0) s_m[wslot] = m;
    __syncthreads();
    const int base = half * 4;
    m = fmaxf(fmaxf(s_m[base], s_m[base + 1]), fmaxf(s_m[base + 2], s_m[base + 3]));

    // warp-level sum of p.y * 2^(p.x - m)
    float e = p.y * ex2f(p.x - m);
    #pragma unroll
    for (int o = 16; o >= 1; o >>= 1)
        e += __shfl_xor_sync(0xffffffffu, e, o);
    if ((t & 31) == 0) s_s[wslot] = e;
    __syncthreads();
    if (j == 0) {
        float s = s_s[base] + s_s[base + 1] + s_s[base + 2] + s_s[base + 3];
        s_lse[half] = LN2 * (m + lg2f(s));
    }
    __syncthreads();
    if (t == 0) {
        const float diag = (*scale_p) * g_diag[r];
        g_contrib[r] = (s_lse[0] - diag) + (s_lse[1] - diag);
    }
}

// ---------------------------------------------------------------------------
// Stage 3: final reduction, 1024 threads with MLP>=4.
// ---------------------------------------------------------------------------
__global__ void __launch_bounds__(1024)
clip_reduce_final(float* __restrict__ out)
{
    __shared__ float red[1024];
    const int t = threadIdx.x;
    const float4* c4 = (const float4*)g_contrib;   // 4096 float4
    float4 v0 = c4[t];
    float4 v1 = c4[t + 1024];
    float4 v2 = c4[t + 2048];
    float4 v3 = c4[t + 3072];
    float s = ((v0.x + v0.y) + (v0.z + v0.w)) + ((v1.x + v1.y) + (v1.z + v1.w))
            + ((v2.x + v2.y) + (v2.z + v2.w)) + ((v3.x + v3.y) + (v3.z + v3.w));
    red[t] = s;  __syncthreads();
    #pragma unroll
    for (int k = 512; k > 0; k >>= 1) { if (t < k) red[t] += red[t + k]; __syncthreads(); }
    if (t == 0) out[0] = red[0] * (0.5f / (float)N_);
}

// ---------------------------------------------------------------------------
extern "C" void kernel_launch(void* const* d_in, const int* in_sizes, int n_in,
                              void* d_out, int out_size)
{
    const float* img   = (const float*)d_in[0];
    const float* txt   = (const float*)d_in[1];
    const float* scale = (const float*)d_in[2];
    float* out = (float*)d_out;

    cudaFuncSetAttribute(clip_gemm_lse, cudaFuncAttributeMaxDynamicSharedMemorySize, SMEM_TOTAL);

    clip_quant<<<N_, 128>>>(img, txt);
    clip_gemm_lse<<<dim3(GT, GT), 256, SMEM_TOTAL>>>(scale);
    clip_finalize<<<N_, 256>>>(scale);
    clip_reduce_final<<<1, 1024>>>(out);
}